// round 7
// baseline (speedup 1.0000x reference)
#include <cuda_runtime.h>
#include <cuda_bf16.h>
#include <cstdint>

// ---------------------------------------------------------------------------
// Problem: B=4, T=2048, C=1024, H=16, D=64.  out = attn(xWq, xWk, xWv) Wo
// GEMMs: mma.sync bf16 (family-portable PTX), hi/lo split, fp32 accum.
// Attention: fp32 SIMT flash kernel.
// ---------------------------------------------------------------------------
#define BB   4
#define TT   2048
#define CC   1024
#define HH   16
#define DD   64
#define MROWS (BB*TT)          // 8192
#define KDIM 1024
#define NDIM 1024

// ---- scratch ---------------------------------------------------------------
__device__ float g_q[BB*HH*TT*DD];
__device__ float g_k[BB*HH*TT*DD];
__device__ float g_v[BB*HH*TT*DD];
__device__ __nv_bfloat16 g_xhi[MROWS*KDIM], g_xlo[MROWS*KDIM];
__device__ __nv_bfloat16 g_yhi[MROWS*KDIM], g_ylo[MROWS*KDIM];
__device__ __nv_bfloat16 g_wqhi[NDIM*KDIM], g_wqlo[NDIM*KDIM];
__device__ __nv_bfloat16 g_wkhi[NDIM*KDIM], g_wklo[NDIM*KDIM];
__device__ __nv_bfloat16 g_wvhi[NDIM*KDIM], g_wvlo[NDIM*KDIM];
__device__ __nv_bfloat16 g_wohi[NDIM*KDIM], g_wolo[NDIM*KDIM];

__device__ __forceinline__ uint32_t smem_u32(const void* p) {
    uint32_t a;
    asm("{ .reg .u64 t; cvta.to.shared.u64 t, %1; cvt.u32.u64 %0, t; }"
        : "=r"(a) : "l"(p));
    return a;
}
__device__ __forceinline__ void ldsm4(uint32_t& r0, uint32_t& r1,
                                      uint32_t& r2, uint32_t& r3, uint32_t addr) {
    asm volatile("ldmatrix.sync.aligned.m8n8.x4.shared.b16 {%0,%1,%2,%3}, [%4];"
                 : "=r"(r0), "=r"(r1), "=r"(r2), "=r"(r3) : "r"(addr));
}
#define MMA_BF16(d, a, b0, b1)                                              \
    asm volatile("mma.sync.aligned.m16n8k16.row.col.f32.bf16.bf16.f32 "     \
                 "{%0,%1,%2,%3}, {%4,%5,%6,%7}, {%8,%9}, {%0,%1,%2,%3};"    \
                 : "+f"((d)[0]), "+f"((d)[1]), "+f"((d)[2]), "+f"((d)[3])   \
                 : "r"((a)[0]), "r"((a)[1]), "r"((a)[2]), "r"((a)[3]),      \
                   "r"(b0), "r"(b1))

// ---------------------------------------------------------------------------
// bf16 hi/lo split (elementwise, float4-vectorized)
// ---------------------------------------------------------------------------
__global__ void split_kernel(const float* __restrict__ src,
                             __nv_bfloat16* __restrict__ hi,
                             __nv_bfloat16* __restrict__ lo, int n)
{
    int i = (blockIdx.x * blockDim.x + threadIdx.x) * 4;
    if (i >= n) return;
    float4 v = *(const float4*)(src + i);
    float xs[4] = {v.x, v.y, v.z, v.w};
    __nv_bfloat16 hs[4], ls[4];
#pragma unroll
    for (int j = 0; j < 4; j++) {
        hs[j] = __float2bfloat16_rn(xs[j]);
        ls[j] = __float2bfloat16_rn(xs[j] - __bfloat162float(hs[j]));
    }
    *(__nv_bfloat162*)(hi + i)     = __halves2bfloat162(hs[0], hs[1]);
    *(__nv_bfloat162*)(hi + i + 2) = __halves2bfloat162(hs[2], hs[3]);
    *(__nv_bfloat162*)(lo + i)     = __halves2bfloat162(ls[0], ls[1]);
    *(__nv_bfloat162*)(lo + i + 2) = __halves2bfloat162(ls[2], ls[3]);
}

// transpose-split for w_o: in [K,N] row-major -> out hi/lo [N,K]
__global__ void split_transpose(const float* __restrict__ W,
                                __nv_bfloat16* __restrict__ hi,
                                __nv_bfloat16* __restrict__ lo)
{
    __shared__ float tile[32][33];
    const int n0 = blockIdx.x * 32, k0 = blockIdx.y * 32;
    const int tx = threadIdx.x, ty = threadIdx.y;
    tile[ty][tx] = W[(k0 + ty) * NDIM + n0 + tx];
    __syncthreads();
    float v = tile[tx][ty];
    __nv_bfloat16 h = __float2bfloat16_rn(v);
    __nv_bfloat16 l = __float2bfloat16_rn(v - __bfloat162float(h));
    const int o = (n0 + ty) * KDIM + k0 + tx;
    hi[o] = h;
    lo[o] = l;
}

// ---------------------------------------------------------------------------
// HMMA GEMM: C[128m x 128n] = Ahi.Bhi^T + Ahi.Blo^T + Alo.Bhi^T over K=1024
// A: [M,K] bf16; B: [N,K] bf16. 256 threads = 8 warps (4m x 2n), warp 32x64.
// smem: per stage 4 tiles of 128 rows x 32 halves, padded stride 40 halves.
//   QKV=true : scatter epilogue to [b,h,t,d] fp32
// ---------------------------------------------------------------------------
#define S_ROWB   80                       // bytes per padded row (40 halves)
#define TILE_B   (128 * S_ROWB)           // 10240 bytes per tile
#define STAGE_B  (4 * TILE_B)             // 40960 bytes per stage

template <bool QKV>
__global__ __launch_bounds__(256)
void hmma_gemm(const __nv_bfloat16* __restrict__ Ahi, const __nv_bfloat16* __restrict__ Alo,
               const __nv_bfloat16* __restrict__ Bhi, const __nv_bfloat16* __restrict__ Blo,
               float* __restrict__ C)
{
    extern __shared__ __align__(128) char sm[];   // 2 stages x 40960B
    const int tid  = threadIdx.x;
    const int wid  = tid >> 5;
    const int lane = tid & 31;
    const int m0   = blockIdx.x * 128;
    const int n0   = blockIdx.y * 128;

    const int wm0 = (wid & 3) * 32;      // warp m origin (2 m16 tiles)
    const int wn0 = (wid >> 2) * 64;     // warp n origin (8 n8 tiles)

    // ---- staging addressing: 512 16B-chunks per tile, 2 per thread --------
    const int idx0 = tid, idx1 = tid + 256;
    const int r0c = idx0 >> 2, c0c = idx0 & 3;
    const int r1c = idx1 >> 2, c1c = idx1 & 3;
    const size_t ga0 = (size_t)(m0 + r0c) * KDIM + c0c * 8;
    const size_t ga1 = (size_t)(m0 + r1c) * KDIM + c1c * 8;
    const size_t gb0 = (size_t)(n0 + r0c) * KDIM + c0c * 8;
    const size_t gb1 = (size_t)(n0 + r1c) * KDIM + c1c * 8;
    const uint32_t s0 = r0c * S_ROWB + c0c * 16;
    const uint32_t s1 = r1c * S_ROWB + c1c * 16;

#define LOADG(P, kt)                                                        \
    {                                                                       \
        const int kc = (kt) * 32;                                           \
        P[0] = *(const uint4*)(Ahi + ga0 + kc); P[1] = *(const uint4*)(Ahi + ga1 + kc); \
        P[2] = *(const uint4*)(Alo + ga0 + kc); P[3] = *(const uint4*)(Alo + ga1 + kc); \
        P[4] = *(const uint4*)(Bhi + gb0 + kc); P[5] = *(const uint4*)(Bhi + gb1 + kc); \
        P[6] = *(const uint4*)(Blo + gb0 + kc); P[7] = *(const uint4*)(Blo + gb1 + kc); \
    }
#define STORES(P, st)                                                       \
    {                                                                       \
        char* b = sm + (st) * STAGE_B;                                      \
        *(uint4*)(b + 0 * TILE_B + s0) = P[0]; *(uint4*)(b + 0 * TILE_B + s1) = P[1]; \
        *(uint4*)(b + 1 * TILE_B + s0) = P[2]; *(uint4*)(b + 1 * TILE_B + s1) = P[3]; \
        *(uint4*)(b + 2 * TILE_B + s0) = P[4]; *(uint4*)(b + 2 * TILE_B + s1) = P[5]; \
        *(uint4*)(b + 3 * TILE_B + s0) = P[6]; *(uint4*)(b + 3 * TILE_B + s1) = P[7]; \
    }

    // ---- ldmatrix addresses (byte offsets within a tile) ------------------
    // A (x4): rows m..m+15, chunks ksub*2 + (lane>>4)
    const uint32_t smb = smem_u32(sm);
    const uint32_t aRow = wm0 + (lane & 15);
    const uint32_t aChunkBase = (lane >> 4);         // 0/1
    // B (x4, two n8 tiles): lane groups g=lane>>3
    const uint32_t g = lane >> 3;
    const uint32_t bRow = wn0 + (lane & 7) + ((g >> 1) << 3);  // +8 for g2,g3
    const uint32_t bChunkBase = (g & 1);

    float acc[2][8][4];
#pragma unroll
    for (int i = 0; i < 2; i++)
#pragma unroll
        for (int j = 0; j < 8; j++)
#pragma unroll
            for (int q = 0; q < 4; q++) acc[i][j][q] = 0.f;

    {
        uint4 P[8];
        LOADG(P, 0);
        STORES(P, 0);
    }
    __syncthreads();

    for (int kt = 0; kt < 32; kt++) {
        const int st = kt & 1;
        uint4 P[8];
        if (kt < 31) LOADG(P, kt + 1);

        const uint32_t base = smb + st * STAGE_B;
#pragma unroll
        for (int ksub = 0; ksub < 2; ksub++) {
            uint32_t ahi[2][4], alo[2][4];
#pragma unroll
            for (int mi = 0; mi < 2; mi++) {
                const uint32_t off = (aRow + mi * 16) * S_ROWB
                                   + (ksub * 2 + aChunkBase) * 16;
                ldsm4(ahi[mi][0], ahi[mi][1], ahi[mi][2], ahi[mi][3],
                      base + 0 * TILE_B + off);
                ldsm4(alo[mi][0], alo[mi][1], alo[mi][2], alo[mi][3],
                      base + 1 * TILE_B + off);
            }
            uint32_t bhi[4][4], blo[4][4];
#pragma unroll
            for (int pj = 0; pj < 4; pj++) {
                const uint32_t off = (bRow + pj * 16) * S_ROWB
                                   + (ksub * 2 + bChunkBase) * 16;
                ldsm4(bhi[pj][0], bhi[pj][1], bhi[pj][2], bhi[pj][3],
                      base + 2 * TILE_B + off);
                ldsm4(blo[pj][0], blo[pj][1], blo[pj][2], blo[pj][3],
                      base + 3 * TILE_B + off);
            }
#pragma unroll
            for (int mi = 0; mi < 2; mi++)
#pragma unroll
                for (int nt = 0; nt < 8; nt++) {
                    const int pj = nt >> 1, hh = (nt & 1) * 2;
                    MMA_BF16(acc[mi][nt], ahi[mi], bhi[pj][hh], bhi[pj][hh + 1]);
                    MMA_BF16(acc[mi][nt], ahi[mi], blo[pj][hh], blo[pj][hh + 1]);
                    MMA_BF16(acc[mi][nt], alo[mi], bhi[pj][hh], bhi[pj][hh + 1]);
                }
        }
        __syncthreads();
        if (kt < 31) {
            STORES(P, st ^ 1);
            __syncthreads();
        }
    }

    // ---- epilogue: d-frag thread mapping: rows lane>>2 (+8), cols (lane&3)*2
#pragma unroll
    for (int mi = 0; mi < 2; mi++) {
#pragma unroll
        for (int nt = 0; nt < 8; nt++) {
            const int mrow0 = m0 + wm0 + mi * 16 + (lane >> 2);
            const int ncol  = n0 + wn0 + nt * 8 + (lane & 3) * 2;
            if (QKV) {
                const int h = ncol >> 6, d = ncol & 63;
#pragma unroll
                for (int half = 0; half < 2; half++) {
                    const int m = mrow0 + half * 8;
                    const int b = m >> 11, t = m & 2047;
                    float* o = C + (((size_t)(b * HH + h) * TT + t) * DD + d);
                    *(float2*)o = make_float2(acc[mi][nt][half * 2],
                                              acc[mi][nt][half * 2 + 1]);
                }
            } else {
#pragma unroll
                for (int half = 0; half < 2; half++) {
                    float* o = C + (size_t)(mrow0 + half * 8) * NDIM + ncol;
                    *(float2*)o = make_float2(acc[mi][nt][half * 2],
                                              acc[mi][nt][half * 2 + 1]);
                }
            }
        }
    }
#undef LOADG
#undef STORES
}

// ---------------------------------------------------------------------------
// Causal flash attention, D=64, 64 q-rows per CTA, 256 threads (4x4/thread).
// grid = (T/64, B*H). Outputs y split into bf16 hi/lo [b,t,h,d].
// ---------------------------------------------------------------------------
__global__ __launch_bounds__(256)
void attn64(const float* __restrict__ Qg, const float* __restrict__ Kg,
            const float* __restrict__ Vg,
            __nv_bfloat16* __restrict__ Yhi, __nv_bfloat16* __restrict__ Ylo)
{
    const int tid = threadIdx.x;
    const int tx  = tid & 15;
    const int ty  = tid >> 4;
    const int qt  = blockIdx.x;
    const int bh  = blockIdx.y;
    const int b   = bh >> 4;
    const int h   = bh & 15;

    const float* q = Qg + (size_t)bh * TT * DD;
    const float* k = Kg + (size_t)bh * TT * DD;
    const float* v = Vg + (size_t)bh * TT * DD;

    __shared__ float QsT[64][64];
    __shared__ float KP[64][64];
    __shared__ float Vs[64][64];

    const int q0 = qt * 64;

    {
        const int r  = tid & 63;
        const int cb = tid >> 6;
#pragma unroll
        for (int i = 0; i < 4; i++) {
            const int cI = cb + i * 4;
            float4 val = *(const float4*)(q + (q0 + r) * 64 + cI * 4);
            QsT[cI * 4 + 0][r] = val.x * 0.125f;
            QsT[cI * 4 + 1][r] = val.y * 0.125f;
            QsT[cI * 4 + 2][r] = val.z * 0.125f;
            QsT[cI * 4 + 3][r] = val.w * 0.125f;
        }
    }

    float accO[4][4];
    float mrow[4], lrow[4];
#pragma unroll
    for (int i = 0; i < 4; i++) {
        mrow[i] = -1e30f; lrow[i] = 0.f;
#pragma unroll
        for (int j = 0; j < 4; j++) accO[i][j] = 0.f;
    }

    for (int kt = 0; kt <= qt; kt++) {
        const int k0 = kt * 64;
        __syncthreads();
        {
            const int r  = tid & 63;
            const int cb = tid >> 6;
#pragma unroll
            for (int i = 0; i < 4; i++) {
                const int cI = cb + i * 4;
                float4 val = *(const float4*)(k + (k0 + r) * 64 + cI * 4);
                KP[cI * 4 + 0][r] = val.x;
                KP[cI * 4 + 1][r] = val.y;
                KP[cI * 4 + 2][r] = val.z;
                KP[cI * 4 + 3][r] = val.w;
            }
#pragma unroll
            for (int i = 0; i < 4; i++) {
                const int idx = tid + i * 256;
                const int rr  = idx >> 4;
                const int cc  = (idx & 15) * 4;
                *(float4*)&Vs[rr][cc] = *(const float4*)(v + (k0 + rr) * 64 + cc);
            }
        }
        __syncthreads();

        float s[4][4];
#pragma unroll
        for (int i = 0; i < 4; i++)
#pragma unroll
            for (int j = 0; j < 4; j++) s[i][j] = 0.f;

#pragma unroll 8
        for (int kk = 0; kk < 64; kk++) {
            float4 qv = *(float4*)&QsT[kk][ty * 4];
            float4 kv = *(float4*)&KP[kk][tx * 4];
            float qa[4] = {qv.x, qv.y, qv.z, qv.w};
            float ka[4] = {kv.x, kv.y, kv.z, kv.w};
#pragma unroll
            for (int i = 0; i < 4; i++)
#pragma unroll
                for (int j = 0; j < 4; j++) s[i][j] += qa[i] * ka[j];
        }

        if (kt == qt) {
#pragma unroll
            for (int i = 0; i < 4; i++)
#pragma unroll
                for (int j = 0; j < 4; j++)
                    if (tx * 4 + j > ty * 4 + i) s[i][j] = -1e30f;
        }

#pragma unroll
        for (int i = 0; i < 4; i++) {
            float mx = fmaxf(fmaxf(s[i][0], s[i][1]), fmaxf(s[i][2], s[i][3]));
#pragma unroll
            for (int o = 8; o >= 1; o >>= 1)
                mx = fmaxf(mx, __shfl_xor_sync(0xffffffffu, mx, o));
            const float mn    = fmaxf(mrow[i], mx);
            const float scale = __expf(mrow[i] - mn);
            float rs = 0.f;
#pragma unroll
            for (int j = 0; j < 4; j++) {
                s[i][j] = __expf(s[i][j] - mn);
                rs += s[i][j];
            }
#pragma unroll
            for (int o = 8; o >= 1; o >>= 1)
                rs += __shfl_xor_sync(0xffffffffu, rs, o);
            lrow[i] = lrow[i] * scale + rs;
            mrow[i] = mn;
#pragma unroll
            for (int j = 0; j < 4; j++) accO[i][j] *= scale;
        }

        __syncthreads();
#pragma unroll
        for (int i = 0; i < 4; i++)
#pragma unroll
            for (int j = 0; j < 4; j++)
                KP[ty * 4 + i][tx * 4 + j] = s[i][j];
        __syncthreads();

#pragma unroll 8
        for (int nn = 0; nn < 64; nn++) {
            float4 vv = *(float4*)&Vs[nn][tx * 4];
            float va[4] = {vv.x, vv.y, vv.z, vv.w};
            float p0 = KP[ty * 4 + 0][nn];
            float p1 = KP[ty * 4 + 1][nn];
            float p2 = KP[ty * 4 + 2][nn];
            float p3 = KP[ty * 4 + 3][nn];
#pragma unroll
            for (int j = 0; j < 4; j++) {
                accO[0][j] += p0 * va[j];
                accO[1][j] += p1 * va[j];
                accO[2][j] += p2 * va[j];
                accO[3][j] += p3 * va[j];
            }
        }
    }

    // ---- epilogue: split-write y[b,t,h,d] as bf16 hi/lo -------------------
#pragma unroll
    for (int i = 0; i < 4; i++) {
        const float inv = 1.0f / lrow[i];
        const int t = q0 + ty * 4 + i;
        const size_t off = ((size_t)(b * TT + t)) * CC + h * DD + tx * 4;
        __nv_bfloat16 hs[4], ls[4];
#pragma unroll
        for (int j = 0; j < 4; j++) {
            float val = accO[i][j] * inv;
            hs[j] = __float2bfloat16_rn(val);
            ls[j] = __float2bfloat16_rn(val - __bfloat162float(hs[j]));
        }
        *(__nv_bfloat162*)(Yhi + off)     = __halves2bfloat162(hs[0], hs[1]);
        *(__nv_bfloat162*)(Yhi + off + 2) = __halves2bfloat162(hs[2], hs[3]);
        *(__nv_bfloat162*)(Ylo + off)     = __halves2bfloat162(ls[0], ls[1]);
        *(__nv_bfloat162*)(Ylo + off + 2) = __halves2bfloat162(ls[2], ls[3]);
    }
}

// ---------------------------------------------------------------------------
// launch
// ---------------------------------------------------------------------------
extern "C" void kernel_launch(void* const* d_in, const int* in_sizes, int n_in,
                              void* d_out, int out_size)
{
    const float* x_q = (const float*)d_in[0];
    const float* w_q = (const float*)d_in[1];
    const float* w_k = (const float*)d_in[2];
    const float* w_v = (const float*)d_in[3];
    const float* w_o = (const float*)d_in[4];
    float* out = (float*)d_out;

    float *gq, *gk, *gv;
    cudaGetSymbolAddress((void**)&gq, g_q);
    cudaGetSymbolAddress((void**)&gk, g_k);
    cudaGetSymbolAddress((void**)&gv, g_v);
    __nv_bfloat16 *xhi, *xlo, *yhi, *ylo;
    __nv_bfloat16 *wqhi, *wqlo, *wkhi, *wklo, *wvhi, *wvlo, *wohi, *wolo;
    cudaGetSymbolAddress((void**)&xhi, g_xhi);  cudaGetSymbolAddress((void**)&xlo, g_xlo);
    cudaGetSymbolAddress((void**)&yhi, g_yhi);  cudaGetSymbolAddress((void**)&ylo, g_ylo);
    cudaGetSymbolAddress((void**)&wqhi, g_wqhi); cudaGetSymbolAddress((void**)&wqlo, g_wqlo);
    cudaGetSymbolAddress((void**)&wkhi, g_wkhi); cudaGetSymbolAddress((void**)&wklo, g_wklo);
    cudaGetSymbolAddress((void**)&wvhi, g_wvhi); cudaGetSymbolAddress((void**)&wvlo, g_wvlo);
    cudaGetSymbolAddress((void**)&wohi, g_wohi); cudaGetSymbolAddress((void**)&wolo, g_wolo);

    const int smem = 2 * STAGE_B;   // 81920
    cudaFuncSetAttribute(hmma_gemm<true>,  cudaFuncAttributeMaxDynamicSharedMemorySize, smem);
    cudaFuncSetAttribute(hmma_gemm<false>, cudaFuncAttributeMaxDynamicSharedMemorySize, smem);

    // splits
    split_kernel<<<(MROWS * KDIM / 4 + 255) / 256, 256>>>(x_q, xhi, xlo, MROWS * KDIM);
    split_kernel<<<(NDIM * KDIM / 4 + 255) / 256, 256>>>(w_q, wqhi, wqlo, NDIM * KDIM);
    split_kernel<<<(NDIM * KDIM / 4 + 255) / 256, 256>>>(w_k, wkhi, wklo, NDIM * KDIM);
    split_kernel<<<(NDIM * KDIM / 4 + 255) / 256, 256>>>(w_v, wvhi, wvlo, NDIM * KDIM);
    split_transpose<<<dim3(32, 32), dim3(32, 32)>>>(w_o, wohi, wolo);

    // projections (HMMA)
    dim3 gridG(MROWS / 128, NDIM / 128);     // 64 x 8
    hmma_gemm<true><<<gridG, 256, smem>>>(xhi, xlo, wqhi, wqlo, gq);
    hmma_gemm<true><<<gridG, 256, smem>>>(xhi, xlo, wkhi, wklo, gk);
    hmma_gemm<true><<<gridG, 256, smem>>>(xhi, xlo, wvhi, wvlo, gv);

    // attention (fp32 SIMT), writes split y
    dim3 gridA(TT / 64, BB * HH);            // 32 x 64
    attn64<<<gridA, 256>>>(gq, gk, gv, yhi, ylo);

    // output projection (HMMA)
    hmma_gemm<false><<<gridG, 256, smem>>>(yhi, ylo, wohi, wolo, out);
}

// round 8
// speedup vs baseline: 1.0004x; 1.0004x over previous
#include <cuda_runtime.h>
#include <cuda_bf16.h>
#include <cstdint>

// ---------------------------------------------------------------------------
// Problem: B=4, T=2048, C=1024, H=16, D=64.  out = attn(xWq, xWk, xWv) Wo
// GEMMs: mma.sync bf16 (family-portable PTX), hi/lo split, fp32 accum.
// Attention: fp32 SIMT flash kernel.
// ---------------------------------------------------------------------------
#define BB   4
#define TT   2048
#define CC   1024
#define HH   16
#define DD   64
#define MROWS (BB*TT)          // 8192
#define KDIM 1024
#define NDIM 1024

// ---- scratch ---------------------------------------------------------------
__device__ float g_q[BB*HH*TT*DD];
__device__ float g_k[BB*HH*TT*DD];
__device__ float g_v[BB*HH*TT*DD];
__device__ __nv_bfloat16 g_xhi[MROWS*KDIM], g_xlo[MROWS*KDIM];
__device__ __nv_bfloat16 g_yhi[MROWS*KDIM], g_ylo[MROWS*KDIM];
__device__ __nv_bfloat16 g_wqhi[NDIM*KDIM], g_wqlo[NDIM*KDIM];
__device__ __nv_bfloat16 g_wkhi[NDIM*KDIM], g_wklo[NDIM*KDIM];
__device__ __nv_bfloat16 g_wvhi[NDIM*KDIM], g_wvlo[NDIM*KDIM];
__device__ __nv_bfloat16 g_wohi[NDIM*KDIM], g_wolo[NDIM*KDIM];

__device__ __forceinline__ uint32_t smem_u32(const void* p) {
    uint32_t a;
    asm("{ .reg .u64 t; cvta.to.shared.u64 t, %1; cvt.u32.u64 %0, t; }"
        : "=r"(a) : "l"(p));
    return a;
}
__device__ __forceinline__ void ldsm4(uint32_t& r0, uint32_t& r1,
                                      uint32_t& r2, uint32_t& r3, uint32_t addr) {
    asm volatile("ldmatrix.sync.aligned.m8n8.x4.shared.b16 {%0,%1,%2,%3}, [%4];"
                 : "=r"(r0), "=r"(r1), "=r"(r2), "=r"(r3) : "r"(addr));
}
#define MMA_BF16(d, a, b0, b1)                                              \
    asm volatile("mma.sync.aligned.m16n8k16.row.col.f32.bf16.bf16.f32 "     \
                 "{%0,%1,%2,%3}, {%4,%5,%6,%7}, {%8,%9}, {%0,%1,%2,%3};"    \
                 : "+f"((d)[0]), "+f"((d)[1]), "+f"((d)[2]), "+f"((d)[3])   \
                 : "r"((a)[0]), "r"((a)[1]), "r"((a)[2]), "r"((a)[3]),      \
                   "r"(b0), "r"(b1))

// ---------------------------------------------------------------------------
// bf16 hi/lo split (elementwise, float4-vectorized)
// ---------------------------------------------------------------------------
__global__ void split_kernel(const float* __restrict__ src,
                             __nv_bfloat16* __restrict__ hi,
                             __nv_bfloat16* __restrict__ lo, int n)
{
    int i = (blockIdx.x * blockDim.x + threadIdx.x) * 4;
    if (i >= n) return;
    float4 v = *(const float4*)(src + i);
    float xs[4] = {v.x, v.y, v.z, v.w};
    __nv_bfloat16 hs[4], ls[4];
#pragma unroll
    for (int j = 0; j < 4; j++) {
        hs[j] = __float2bfloat16_rn(xs[j]);
        ls[j] = __float2bfloat16_rn(xs[j] - __bfloat162float(hs[j]));
    }
    *(__nv_bfloat162*)(hi + i)     = __halves2bfloat162(hs[0], hs[1]);
    *(__nv_bfloat162*)(hi + i + 2) = __halves2bfloat162(hs[2], hs[3]);
    *(__nv_bfloat162*)(lo + i)     = __halves2bfloat162(ls[0], ls[1]);
    *(__nv_bfloat162*)(lo + i + 2) = __halves2bfloat162(ls[2], ls[3]);
}

// transpose-split for w_o: in [K,N] row-major -> out hi/lo [N,K]
__global__ void split_transpose(const float* __restrict__ W,
                                __nv_bfloat16* __restrict__ hi,
                                __nv_bfloat16* __restrict__ lo)
{
    __shared__ float tile[32][33];
    const int n0 = blockIdx.x * 32, k0 = blockIdx.y * 32;
    const int tx = threadIdx.x, ty = threadIdx.y;
    tile[ty][tx] = W[(k0 + ty) * NDIM + n0 + tx];
    __syncthreads();
    float v = tile[tx][ty];
    __nv_bfloat16 h = __float2bfloat16_rn(v);
    __nv_bfloat16 l = __float2bfloat16_rn(v - __bfloat162float(h));
    const int o = (n0 + ty) * KDIM + k0 + tx;
    hi[o] = h;
    lo[o] = l;
}

// ---------------------------------------------------------------------------
// HMMA GEMM: C[128m x 128n] = Ahi.Bhi^T + Ahi.Blo^T + Alo.Bhi^T over K=1024
// A: [M,K] bf16; B: [N,K] bf16. 256 threads = 8 warps (4m x 2n), warp 32x64.
// smem: per stage 4 tiles of 128 rows x 32 halves, padded stride 40 halves.
//   QKV=true : scatter epilogue to [b,h,t,d] fp32
// ---------------------------------------------------------------------------
#define S_ROWB   80                       // bytes per padded row (40 halves)
#define TILE_B   (128 * S_ROWB)           // 10240 bytes per tile
#define STAGE_B  (4 * TILE_B)             // 40960 bytes per stage

template <bool QKV>
__global__ __launch_bounds__(256)
void hmma_gemm(const __nv_bfloat16* __restrict__ Ahi, const __nv_bfloat16* __restrict__ Alo,
               const __nv_bfloat16* __restrict__ Bhi, const __nv_bfloat16* __restrict__ Blo,
               float* __restrict__ C)
{
    extern __shared__ __align__(128) char sm[];   // 2 stages x 40960B
    const int tid  = threadIdx.x;
    const int wid  = tid >> 5;
    const int lane = tid & 31;
    const int m0   = blockIdx.x * 128;
    const int n0   = blockIdx.y * 128;

    const int wm0 = (wid & 3) * 32;      // warp m origin (2 m16 tiles)
    const int wn0 = (wid >> 2) * 64;     // warp n origin (8 n8 tiles)

    // ---- staging addressing: 512 16B-chunks per tile, 2 per thread --------
    const int idx0 = tid, idx1 = tid + 256;
    const int r0c = idx0 >> 2, c0c = idx0 & 3;
    const int r1c = idx1 >> 2, c1c = idx1 & 3;
    const size_t ga0 = (size_t)(m0 + r0c) * KDIM + c0c * 8;
    const size_t ga1 = (size_t)(m0 + r1c) * KDIM + c1c * 8;
    const size_t gb0 = (size_t)(n0 + r0c) * KDIM + c0c * 8;
    const size_t gb1 = (size_t)(n0 + r1c) * KDIM + c1c * 8;
    const uint32_t s0 = r0c * S_ROWB + c0c * 16;
    const uint32_t s1 = r1c * S_ROWB + c1c * 16;

#define LOADG(P, kt)                                                        \
    {                                                                       \
        const int kc = (kt) * 32;                                           \
        P[0] = *(const uint4*)(Ahi + ga0 + kc); P[1] = *(const uint4*)(Ahi + ga1 + kc); \
        P[2] = *(const uint4*)(Alo + ga0 + kc); P[3] = *(const uint4*)(Alo + ga1 + kc); \
        P[4] = *(const uint4*)(Bhi + gb0 + kc); P[5] = *(const uint4*)(Bhi + gb1 + kc); \
        P[6] = *(const uint4*)(Blo + gb0 + kc); P[7] = *(const uint4*)(Blo + gb1 + kc); \
    }
#define STORES(P, st)                                                       \
    {                                                                       \
        char* b = sm + (st) * STAGE_B;                                      \
        *(uint4*)(b + 0 * TILE_B + s0) = P[0]; *(uint4*)(b + 0 * TILE_B + s1) = P[1]; \
        *(uint4*)(b + 1 * TILE_B + s0) = P[2]; *(uint4*)(b + 1 * TILE_B + s1) = P[3]; \
        *(uint4*)(b + 2 * TILE_B + s0) = P[4]; *(uint4*)(b + 2 * TILE_B + s1) = P[5]; \
        *(uint4*)(b + 3 * TILE_B + s0) = P[6]; *(uint4*)(b + 3 * TILE_B + s1) = P[7]; \
    }

    // ---- ldmatrix addresses (byte offsets within a tile) ------------------
    // A (x4): rows m..m+15, chunks ksub*2 + (lane>>4)
    const uint32_t smb = smem_u32(sm);
    const uint32_t aRow = wm0 + (lane & 15);
    const uint32_t aChunkBase = (lane >> 4);         // 0/1
    // B (x4, two n8 tiles): lane groups g=lane>>3
    const uint32_t g = lane >> 3;
    const uint32_t bRow = wn0 + (lane & 7) + ((g >> 1) << 3);  // +8 for g2,g3
    const uint32_t bChunkBase = (g & 1);

    float acc[2][8][4];
#pragma unroll
    for (int i = 0; i < 2; i++)
#pragma unroll
        for (int j = 0; j < 8; j++)
#pragma unroll
            for (int q = 0; q < 4; q++) acc[i][j][q] = 0.f;

    {
        uint4 P[8];
        LOADG(P, 0);
        STORES(P, 0);
    }
    __syncthreads();

    for (int kt = 0; kt < 32; kt++) {
        const int st = kt & 1;
        uint4 P[8];
        if (kt < 31) LOADG(P, kt + 1);

        const uint32_t base = smb + st * STAGE_B;
#pragma unroll
        for (int ksub = 0; ksub < 2; ksub++) {
            uint32_t ahi[2][4], alo[2][4];
#pragma unroll
            for (int mi = 0; mi < 2; mi++) {
                const uint32_t off = (aRow + mi * 16) * S_ROWB
                                   + (ksub * 2 + aChunkBase) * 16;
                ldsm4(ahi[mi][0], ahi[mi][1], ahi[mi][2], ahi[mi][3],
                      base + 0 * TILE_B + off);
                ldsm4(alo[mi][0], alo[mi][1], alo[mi][2], alo[mi][3],
                      base + 1 * TILE_B + off);
            }
            uint32_t bhi[4][4], blo[4][4];
#pragma unroll
            for (int pj = 0; pj < 4; pj++) {
                const uint32_t off = (bRow + pj * 16) * S_ROWB
                                   + (ksub * 2 + bChunkBase) * 16;
                ldsm4(bhi[pj][0], bhi[pj][1], bhi[pj][2], bhi[pj][3],
                      base + 2 * TILE_B + off);
                ldsm4(blo[pj][0], blo[pj][1], blo[pj][2], blo[pj][3],
                      base + 3 * TILE_B + off);
            }
#pragma unroll
            for (int mi = 0; mi < 2; mi++)
#pragma unroll
                for (int nt = 0; nt < 8; nt++) {
                    const int pj = nt >> 1, hh = (nt & 1) * 2;
                    MMA_BF16(acc[mi][nt], ahi[mi], bhi[pj][hh], bhi[pj][hh + 1]);
                    MMA_BF16(acc[mi][nt], ahi[mi], blo[pj][hh], blo[pj][hh + 1]);
                    MMA_BF16(acc[mi][nt], alo[mi], bhi[pj][hh], bhi[pj][hh + 1]);
                }
        }
        __syncthreads();
        if (kt < 31) {
            STORES(P, st ^ 1);
            __syncthreads();
        }
    }

    // ---- epilogue: d-frag thread mapping: rows lane>>2 (+8), cols (lane&3)*2
#pragma unroll
    for (int mi = 0; mi < 2; mi++) {
#pragma unroll
        for (int nt = 0; nt < 8; nt++) {
            const int mrow0 = m0 + wm0 + mi * 16 + (lane >> 2);
            const int ncol  = n0 + wn0 + nt * 8 + (lane & 3) * 2;
            if (QKV) {
                const int h = ncol >> 6, d = ncol & 63;
#pragma unroll
                for (int half = 0; half < 2; half++) {
                    const int m = mrow0 + half * 8;
                    const int b = m >> 11, t = m & 2047;
                    float* o = C + (((size_t)(b * HH + h) * TT + t) * DD + d);
                    *(float2*)o = make_float2(acc[mi][nt][half * 2],
                                              acc[mi][nt][half * 2 + 1]);
                }
            } else {
#pragma unroll
                for (int half = 0; half < 2; half++) {
                    float* o = C + (size_t)(mrow0 + half * 8) * NDIM + ncol;
                    *(float2*)o = make_float2(acc[mi][nt][half * 2],
                                              acc[mi][nt][half * 2 + 1]);
                }
            }
        }
    }
#undef LOADG
#undef STORES
}

// ---------------------------------------------------------------------------
// Causal flash attention, D=64, 64 q-rows per CTA, 256 threads (4x4/thread).
// grid = (T/64, B*H). Outputs y split into bf16 hi/lo [b,t,h,d].
// ---------------------------------------------------------------------------
__global__ __launch_bounds__(256)
void attn64(const float* __restrict__ Qg, const float* __restrict__ Kg,
            const float* __restrict__ Vg,
            __nv_bfloat16* __restrict__ Yhi, __nv_bfloat16* __restrict__ Ylo)
{
    const int tid = threadIdx.x;
    const int tx  = tid & 15;
    const int ty  = tid >> 4;
    const int qt  = blockIdx.x;
    const int bh  = blockIdx.y;
    const int b   = bh >> 4;
    const int h   = bh & 15;

    const float* q = Qg + (size_t)bh * TT * DD;
    const float* k = Kg + (size_t)bh * TT * DD;
    const float* v = Vg + (size_t)bh * TT * DD;

    __shared__ float QsT[64][64];
    __shared__ float KP[64][64];
    __shared__ float Vs[64][64];

    const int q0 = qt * 64;

    {
        const int r  = tid & 63;
        const int cb = tid >> 6;
#pragma unroll
        for (int i = 0; i < 4; i++) {
            const int cI = cb + i * 4;
            float4 val = *(const float4*)(q + (q0 + r) * 64 + cI * 4);
            QsT[cI * 4 + 0][r] = val.x * 0.125f;
            QsT[cI * 4 + 1][r] = val.y * 0.125f;
            QsT[cI * 4 + 2][r] = val.z * 0.125f;
            QsT[cI * 4 + 3][r] = val.w * 0.125f;
        }
    }

    float accO[4][4];
    float mrow[4], lrow[4];
#pragma unroll
    for (int i = 0; i < 4; i++) {
        mrow[i] = -1e30f; lrow[i] = 0.f;
#pragma unroll
        for (int j = 0; j < 4; j++) accO[i][j] = 0.f;
    }

    for (int kt = 0; kt <= qt; kt++) {
        const int k0 = kt * 64;
        __syncthreads();
        {
            const int r  = tid & 63;
            const int cb = tid >> 6;
#pragma unroll
            for (int i = 0; i < 4; i++) {
                const int cI = cb + i * 4;
                float4 val = *(const float4*)(k + (k0 + r) * 64 + cI * 4);
                KP[cI * 4 + 0][r] = val.x;
                KP[cI * 4 + 1][r] = val.y;
                KP[cI * 4 + 2][r] = val.z;
                KP[cI * 4 + 3][r] = val.w;
            }
#pragma unroll
            for (int i = 0; i < 4; i++) {
                const int idx = tid + i * 256;
                const int rr  = idx >> 4;
                const int cc  = (idx & 15) * 4;
                *(float4*)&Vs[rr][cc] = *(const float4*)(v + (k0 + rr) * 64 + cc);
            }
        }
        __syncthreads();

        float s[4][4];
#pragma unroll
        for (int i = 0; i < 4; i++)
#pragma unroll
            for (int j = 0; j < 4; j++) s[i][j] = 0.f;

#pragma unroll 8
        for (int kk = 0; kk < 64; kk++) {
            float4 qv = *(float4*)&QsT[kk][ty * 4];
            float4 kv = *(float4*)&KP[kk][tx * 4];
            float qa[4] = {qv.x, qv.y, qv.z, qv.w};
            float ka[4] = {kv.x, kv.y, kv.z, kv.w};
#pragma unroll
            for (int i = 0; i < 4; i++)
#pragma unroll
                for (int j = 0; j < 4; j++) s[i][j] += qa[i] * ka[j];
        }

        if (kt == qt) {
#pragma unroll
            for (int i = 0; i < 4; i++)
#pragma unroll
                for (int j = 0; j < 4; j++)
                    if (tx * 4 + j > ty * 4 + i) s[i][j] = -1e30f;
        }

#pragma unroll
        for (int i = 0; i < 4; i++) {
            float mx = fmaxf(fmaxf(s[i][0], s[i][1]), fmaxf(s[i][2], s[i][3]));
#pragma unroll
            for (int o = 8; o >= 1; o >>= 1)
                mx = fmaxf(mx, __shfl_xor_sync(0xffffffffu, mx, o));
            const float mn    = fmaxf(mrow[i], mx);
            const float scale = __expf(mrow[i] - mn);
            float rs = 0.f;
#pragma unroll
            for (int j = 0; j < 4; j++) {
                s[i][j] = __expf(s[i][j] - mn);
                rs += s[i][j];
            }
#pragma unroll
            for (int o = 8; o >= 1; o >>= 1)
                rs += __shfl_xor_sync(0xffffffffu, rs, o);
            lrow[i] = lrow[i] * scale + rs;
            mrow[i] = mn;
#pragma unroll
            for (int j = 0; j < 4; j++) accO[i][j] *= scale;
        }

        __syncthreads();
#pragma unroll
        for (int i = 0; i < 4; i++)
#pragma unroll
            for (int j = 0; j < 4; j++)
                KP[ty * 4 + i][tx * 4 + j] = s[i][j];
        __syncthreads();

#pragma unroll 8
        for (int nn = 0; nn < 64; nn++) {
            float4 vv = *(float4*)&Vs[nn][tx * 4];
            float va[4] = {vv.x, vv.y, vv.z, vv.w};
            float p0 = KP[ty * 4 + 0][nn];
            float p1 = KP[ty * 4 + 1][nn];
            float p2 = KP[ty * 4 + 2][nn];
            float p3 = KP[ty * 4 + 3][nn];
#pragma unroll
            for (int j = 0; j < 4; j++) {
                accO[0][j] += p0 * va[j];
                accO[1][j] += p1 * va[j];
                accO[2][j] += p2 * va[j];
                accO[3][j] += p3 * va[j];
            }
        }
    }

    // ---- epilogue: split-write y[b,t,h,d] as bf16 hi/lo -------------------
#pragma unroll
    for (int i = 0; i < 4; i++) {
        const float inv = 1.0f / lrow[i];
        const int t = q0 + ty * 4 + i;
        const size_t off = ((size_t)(b * TT + t)) * CC + h * DD + tx * 4;
        __nv_bfloat16 hs[4], ls[4];
#pragma unroll
        for (int j = 0; j < 4; j++) {
            float val = accO[i][j] * inv;
            hs[j] = __float2bfloat16_rn(val);
            ls[j] = __float2bfloat16_rn(val - __bfloat162float(hs[j]));
        }
        *(__nv_bfloat162*)(Yhi + off)     = __halves2bfloat162(hs[0], hs[1]);
        *(__nv_bfloat162*)(Yhi + off + 2) = __halves2bfloat162(hs[2], hs[3]);
        *(__nv_bfloat162*)(Ylo + off)     = __halves2bfloat162(ls[0], ls[1]);
        *(__nv_bfloat162*)(Ylo + off + 2) = __halves2bfloat162(ls[2], ls[3]);
    }
}

// ---------------------------------------------------------------------------
// launch
// ---------------------------------------------------------------------------
extern "C" void kernel_launch(void* const* d_in, const int* in_sizes, int n_in,
                              void* d_out, int out_size)
{
    const float* x_q = (const float*)d_in[0];
    const float* w_q = (const float*)d_in[1];
    const float* w_k = (const float*)d_in[2];
    const float* w_v = (const float*)d_in[3];
    const float* w_o = (const float*)d_in[4];
    float* out = (float*)d_out;

    float *gq, *gk, *gv;
    cudaGetSymbolAddress((void**)&gq, g_q);
    cudaGetSymbolAddress((void**)&gk, g_k);
    cudaGetSymbolAddress((void**)&gv, g_v);
    __nv_bfloat16 *xhi, *xlo, *yhi, *ylo;
    __nv_bfloat16 *wqhi, *wqlo, *wkhi, *wklo, *wvhi, *wvlo, *wohi, *wolo;
    cudaGetSymbolAddress((void**)&xhi, g_xhi);  cudaGetSymbolAddress((void**)&xlo, g_xlo);
    cudaGetSymbolAddress((void**)&yhi, g_yhi);  cudaGetSymbolAddress((void**)&ylo, g_ylo);
    cudaGetSymbolAddress((void**)&wqhi, g_wqhi); cudaGetSymbolAddress((void**)&wqlo, g_wqlo);
    cudaGetSymbolAddress((void**)&wkhi, g_wkhi); cudaGetSymbolAddress((void**)&wklo, g_wklo);
    cudaGetSymbolAddress((void**)&wvhi, g_wvhi); cudaGetSymbolAddress((void**)&wvlo, g_wvlo);
    cudaGetSymbolAddress((void**)&wohi, g_wohi); cudaGetSymbolAddress((void**)&wolo, g_wolo);

    const int smem = 2 * STAGE_B;   // 81920
    cudaFuncSetAttribute(hmma_gemm<true>,  cudaFuncAttributeMaxDynamicSharedMemorySize, smem);
    cudaFuncSetAttribute(hmma_gemm<false>, cudaFuncAttributeMaxDynamicSharedMemorySize, smem);

    // splits
    split_kernel<<<(MROWS * KDIM / 4 + 255) / 256, 256>>>(x_q, xhi, xlo, MROWS * KDIM);
    split_kernel<<<(NDIM * KDIM / 4 + 255) / 256, 256>>>(w_q, wqhi, wqlo, NDIM * KDIM);
    split_kernel<<<(NDIM * KDIM / 4 + 255) / 256, 256>>>(w_k, wkhi, wklo, NDIM * KDIM);
    split_kernel<<<(NDIM * KDIM / 4 + 255) / 256, 256>>>(w_v, wvhi, wvlo, NDIM * KDIM);
    split_transpose<<<dim3(32, 32), dim3(32, 32)>>>(w_o, wohi, wolo);

    // projections (HMMA)
    dim3 gridG(MROWS / 128, NDIM / 128);     // 64 x 8
    hmma_gemm<true><<<gridG, 256, smem>>>(xhi, xlo, wqhi, wqlo, gq);
    hmma_gemm<true><<<gridG, 256, smem>>>(xhi, xlo, wkhi, wklo, gk);
    hmma_gemm<true><<<gridG, 256, smem>>>(xhi, xlo, wvhi, wvlo, gv);

    // attention (fp32 SIMT), writes split y
    dim3 gridA(TT / 64, BB * HH);            // 32 x 64
    attn64<<<gridA, 256>>>(gq, gk, gv, yhi, ylo);

    // output projection (HMMA)
    hmma_gemm<false><<<gridG, 256, smem>>>(yhi, ylo, wohi, wolo, out);
}

// round 9
// speedup vs baseline: 1.6282x; 1.6276x over previous
#include <cuda_runtime.h>
#include <cuda_bf16.h>
#include <cstdint>

// ---------------------------------------------------------------------------
// Problem: B=4, T=2048, C=1024, H=16, D=64.  out = attn(xWq, xWk, xWv) Wo
// All four GEMMs + attention on HMMA (mma.sync bf16, 3-term hi/lo split).
// ---------------------------------------------------------------------------
#define BB   4
#define TT   2048
#define CC   1024
#define HH   16
#define DD   64
#define MROWS (BB*TT)          // 8192
#define KDIM 1024
#define NDIM 1024

// ---- scratch ---------------------------------------------------------------
__device__ __nv_bfloat16 g_qhi[BB*HH*TT*DD], g_qlo[BB*HH*TT*DD];
__device__ __nv_bfloat16 g_khi[BB*HH*TT*DD], g_klo[BB*HH*TT*DD];
__device__ __nv_bfloat16 g_vhi[BB*HH*TT*DD], g_vlo[BB*HH*TT*DD];
__device__ __nv_bfloat16 g_xhi[MROWS*KDIM], g_xlo[MROWS*KDIM];
__device__ __nv_bfloat16 g_yhi[MROWS*KDIM], g_ylo[MROWS*KDIM];
__device__ __nv_bfloat16 g_wqhi[NDIM*KDIM], g_wqlo[NDIM*KDIM];
__device__ __nv_bfloat16 g_wkhi[NDIM*KDIM], g_wklo[NDIM*KDIM];
__device__ __nv_bfloat16 g_wvhi[NDIM*KDIM], g_wvlo[NDIM*KDIM];
__device__ __nv_bfloat16 g_wohi[NDIM*KDIM], g_wolo[NDIM*KDIM];

__device__ __forceinline__ uint32_t smem_u32(const void* p) {
    uint32_t a;
    asm("{ .reg .u64 t; cvta.to.shared.u64 t, %1; cvt.u32.u64 %0, t; }"
        : "=r"(a) : "l"(p));
    return a;
}
__device__ __forceinline__ void ldsm4(uint32_t& r0, uint32_t& r1,
                                      uint32_t& r2, uint32_t& r3, uint32_t addr) {
    asm volatile("ldmatrix.sync.aligned.m8n8.x4.shared.b16 {%0,%1,%2,%3}, [%4];"
                 : "=r"(r0), "=r"(r1), "=r"(r2), "=r"(r3) : "r"(addr));
}
__device__ __forceinline__ void ldsm4t(uint32_t& r0, uint32_t& r1,
                                       uint32_t& r2, uint32_t& r3, uint32_t addr) {
    asm volatile("ldmatrix.sync.aligned.m8n8.x4.trans.shared.b16 {%0,%1,%2,%3}, [%4];"
                 : "=r"(r0), "=r"(r1), "=r"(r2), "=r"(r3) : "r"(addr));
}
#define MMA_BF16(d, a, b0, b1)                                              \
    asm volatile("mma.sync.aligned.m16n8k16.row.col.f32.bf16.bf16.f32 "     \
                 "{%0,%1,%2,%3}, {%4,%5,%6,%7}, {%8,%9}, {%0,%1,%2,%3};"    \
                 : "+f"((d)[0]), "+f"((d)[1]), "+f"((d)[2]), "+f"((d)[3])   \
                 : "r"((a)[0]), "r"((a)[1]), "r"((a)[2]), "r"((a)[3]),      \
                   "r"(b0), "r"(b1))
__device__ __forceinline__ void cpa16(uint32_t dst, const void* src) {
    asm volatile("cp.async.ca.shared.global [%0], [%1], 16;"
                 :: "r"(dst), "l"(src));
}
#define CP_COMMIT() asm volatile("cp.async.commit_group;")
#define CP_WAIT(n)  asm volatile("cp.async.wait_group %0;" :: "n"(n))
__device__ __forceinline__ float ex2f(float x) {
    float y; asm("ex2.approx.ftz.f32 %0, %1;" : "=f"(y) : "f"(x)); return y;
}
__device__ __forceinline__ void split2(float a, float b, uint32_t& hi, uint32_t& lo) {
    __nv_bfloat16 ha = __float2bfloat16_rn(a), hb = __float2bfloat16_rn(b);
    __nv_bfloat16 la = __float2bfloat16_rn(a - __bfloat162float(ha));
    __nv_bfloat16 lb = __float2bfloat16_rn(b - __bfloat162float(hb));
    __nv_bfloat162 vh = __halves2bfloat162(ha, hb), vl = __halves2bfloat162(la, lb);
    hi = *(uint32_t*)&vh; lo = *(uint32_t*)&vl;
}

// ---------------------------------------------------------------------------
// bf16 hi/lo split kernels
// ---------------------------------------------------------------------------
__global__ void split_kernel(const float* __restrict__ src,
                             __nv_bfloat16* __restrict__ hi,
                             __nv_bfloat16* __restrict__ lo, int n)
{
    int i = (blockIdx.x * blockDim.x + threadIdx.x) * 4;
    if (i >= n) return;
    float4 v = *(const float4*)(src + i);
    float xs[4] = {v.x, v.y, v.z, v.w};
    __nv_bfloat16 hs[4], ls[4];
#pragma unroll
    for (int j = 0; j < 4; j++) {
        hs[j] = __float2bfloat16_rn(xs[j]);
        ls[j] = __float2bfloat16_rn(xs[j] - __bfloat162float(hs[j]));
    }
    *(__nv_bfloat162*)(hi + i)     = __halves2bfloat162(hs[0], hs[1]);
    *(__nv_bfloat162*)(hi + i + 2) = __halves2bfloat162(hs[2], hs[3]);
    *(__nv_bfloat162*)(lo + i)     = __halves2bfloat162(ls[0], ls[1]);
    *(__nv_bfloat162*)(lo + i + 2) = __halves2bfloat162(ls[2], ls[3]);
}

__global__ void split_transpose(const float* __restrict__ W,
                                __nv_bfloat16* __restrict__ hi,
                                __nv_bfloat16* __restrict__ lo)
{
    __shared__ float tile[32][33];
    const int n0 = blockIdx.x * 32, k0 = blockIdx.y * 32;
    const int tx = threadIdx.x, ty = threadIdx.y;
    tile[ty][tx] = W[(k0 + ty) * NDIM + n0 + tx];
    __syncthreads();
    float v = tile[tx][ty];
    __nv_bfloat16 h = __float2bfloat16_rn(v);
    __nv_bfloat16 l = __float2bfloat16_rn(v - __bfloat162float(h));
    const int o = (n0 + ty) * KDIM + k0 + tx;
    hi[o] = h;
    lo[o] = l;
}

// ---------------------------------------------------------------------------
// HMMA GEMM (same as R8 core). QKV=true: split-bf16 scatter epilogue with
// preScale (Q gets 0.125*log2e folded in).
// ---------------------------------------------------------------------------
#define S_ROWB   80
#define TILE_B   (128 * S_ROWB)
#define STAGE_B  (4 * TILE_B)

template <bool QKV>
__global__ __launch_bounds__(256)
void hmma_gemm(const __nv_bfloat16* __restrict__ Ahi, const __nv_bfloat16* __restrict__ Alo,
               const __nv_bfloat16* __restrict__ Bhi, const __nv_bfloat16* __restrict__ Blo,
               float* __restrict__ C,
               __nv_bfloat16* __restrict__ Chi, __nv_bfloat16* __restrict__ Clo,
               float preScale)
{
    extern __shared__ __align__(128) char sm[];
    const int tid  = threadIdx.x;
    const int wid  = tid >> 5;
    const int lane = tid & 31;
    const int m0   = blockIdx.x * 128;
    const int n0   = blockIdx.y * 128;

    const int wm0 = (wid & 3) * 32;
    const int wn0 = (wid >> 2) * 64;

    const int idx0 = tid, idx1 = tid + 256;
    const int r0c = idx0 >> 2, c0c = idx0 & 3;
    const int r1c = idx1 >> 2, c1c = idx1 & 3;
    const size_t ga0 = (size_t)(m0 + r0c) * KDIM + c0c * 8;
    const size_t ga1 = (size_t)(m0 + r1c) * KDIM + c1c * 8;
    const size_t gb0 = (size_t)(n0 + r0c) * KDIM + c0c * 8;
    const size_t gb1 = (size_t)(n0 + r1c) * KDIM + c1c * 8;
    const uint32_t s0 = r0c * S_ROWB + c0c * 16;
    const uint32_t s1 = r1c * S_ROWB + c1c * 16;

#define LOADG(P, kt)                                                        \
    {                                                                       \
        const int kc = (kt) * 32;                                           \
        P[0] = *(const uint4*)(Ahi + ga0 + kc); P[1] = *(const uint4*)(Ahi + ga1 + kc); \
        P[2] = *(const uint4*)(Alo + ga0 + kc); P[3] = *(const uint4*)(Alo + ga1 + kc); \
        P[4] = *(const uint4*)(Bhi + gb0 + kc); P[5] = *(const uint4*)(Bhi + gb1 + kc); \
        P[6] = *(const uint4*)(Blo + gb0 + kc); P[7] = *(const uint4*)(Blo + gb1 + kc); \
    }
#define STORES(P, st)                                                       \
    {                                                                       \
        char* b = sm + (st) * STAGE_B;                                      \
        *(uint4*)(b + 0 * TILE_B + s0) = P[0]; *(uint4*)(b + 0 * TILE_B + s1) = P[1]; \
        *(uint4*)(b + 1 * TILE_B + s0) = P[2]; *(uint4*)(b + 1 * TILE_B + s1) = P[3]; \
        *(uint4*)(b + 2 * TILE_B + s0) = P[4]; *(uint4*)(b + 2 * TILE_B + s1) = P[5]; \
        *(uint4*)(b + 3 * TILE_B + s0) = P[6]; *(uint4*)(b + 3 * TILE_B + s1) = P[7]; \
    }

    const uint32_t smb = smem_u32(sm);
    const uint32_t aRow = wm0 + (lane & 15);
    const uint32_t aChunkBase = (lane >> 4);
    const uint32_t g = lane >> 3;
    const uint32_t bRow = wn0 + (lane & 7) + ((g >> 1) << 3);
    const uint32_t bChunkBase = (g & 1);

    float acc[2][8][4];
#pragma unroll
    for (int i = 0; i < 2; i++)
#pragma unroll
        for (int j = 0; j < 8; j++)
#pragma unroll
            for (int q = 0; q < 4; q++) acc[i][j][q] = 0.f;

    {
        uint4 P[8];
        LOADG(P, 0);
        STORES(P, 0);
    }
    __syncthreads();

    for (int kt = 0; kt < 32; kt++) {
        const int st = kt & 1;
        uint4 P[8];
        if (kt < 31) LOADG(P, kt + 1);

        const uint32_t base = smb + st * STAGE_B;
#pragma unroll
        for (int ksub = 0; ksub < 2; ksub++) {
            uint32_t ahi[2][4], alo[2][4];
#pragma unroll
            for (int mi = 0; mi < 2; mi++) {
                const uint32_t off = (aRow + mi * 16) * S_ROWB
                                   + (ksub * 2 + aChunkBase) * 16;
                ldsm4(ahi[mi][0], ahi[mi][1], ahi[mi][2], ahi[mi][3],
                      base + 0 * TILE_B + off);
                ldsm4(alo[mi][0], alo[mi][1], alo[mi][2], alo[mi][3],
                      base + 1 * TILE_B + off);
            }
            uint32_t bhi[4][4], blo[4][4];
#pragma unroll
            for (int pj = 0; pj < 4; pj++) {
                const uint32_t off = (bRow + pj * 16) * S_ROWB
                                   + (ksub * 2 + bChunkBase) * 16;
                ldsm4(bhi[pj][0], bhi[pj][1], bhi[pj][2], bhi[pj][3],
                      base + 2 * TILE_B + off);
                ldsm4(blo[pj][0], blo[pj][1], blo[pj][2], blo[pj][3],
                      base + 3 * TILE_B + off);
            }
#pragma unroll
            for (int mi = 0; mi < 2; mi++)
#pragma unroll
                for (int nt = 0; nt < 8; nt++) {
                    const int pj = nt >> 1, hh = (nt & 1) * 2;
                    MMA_BF16(acc[mi][nt], ahi[mi], bhi[pj][hh], bhi[pj][hh + 1]);
                    MMA_BF16(acc[mi][nt], ahi[mi], blo[pj][hh], blo[pj][hh + 1]);
                    MMA_BF16(acc[mi][nt], alo[mi], bhi[pj][hh], bhi[pj][hh + 1]);
                }
        }
        __syncthreads();
        if (kt < 31) {
            STORES(P, st ^ 1);
            __syncthreads();
        }
    }

#pragma unroll
    for (int mi = 0; mi < 2; mi++) {
#pragma unroll
        for (int nt = 0; nt < 8; nt++) {
            const int mrow0 = m0 + wm0 + mi * 16 + (lane >> 2);
            const int ncol  = n0 + wn0 + nt * 8 + (lane & 3) * 2;
            if (QKV) {
                const int h = ncol >> 6, d = ncol & 63;
#pragma unroll
                for (int half = 0; half < 2; half++) {
                    const int m = mrow0 + half * 8;
                    const int b = m >> 11, t = m & 2047;
                    const size_t off = (((size_t)(b * HH + h) * TT + t) * DD + d);
                    uint32_t hh, ll;
                    split2(acc[mi][nt][half * 2] * preScale,
                           acc[mi][nt][half * 2 + 1] * preScale, hh, ll);
                    *(uint32_t*)(Chi + off) = hh;
                    *(uint32_t*)(Clo + off) = ll;
                }
            } else {
#pragma unroll
                for (int half = 0; half < 2; half++) {
                    float* o = C + (size_t)(mrow0 + half * 8) * NDIM + ncol;
                    *(float2*)o = make_float2(acc[mi][nt][half * 2],
                                              acc[mi][nt][half * 2 + 1]);
                }
            }
        }
    }
#undef LOADG
#undef STORES
}

// ---------------------------------------------------------------------------
// HMMA flash attention. CTA = 64 q-rows, 4 warps (16 rows each), D=64.
// Q frags persistent in regs; K/V cp.async double-buffered; P converts
// in-register from S accum frags. 3-term bf16 split everywhere.
// grid = (32 qtiles [reversed], 64 bh), block 128.
// ---------------------------------------------------------------------------
#define ASTR_H  72                         // padded halves per row
#define ASTRB   144                        // bytes per row
#define ATILE_B (64 * ASTRB)               // 9216
#define ASTAGE_B (4 * ATILE_B)             // 36864
#define AQ_OFF  (2 * ASTAGE_B)             // Qhi at 73728, Qlo at +9216
#define ASMEM_TOTAL (AQ_OFF + 2 * ATILE_B) // 92160

__global__ __launch_bounds__(128)
void attn_mma(const __nv_bfloat16* __restrict__ Qhi, const __nv_bfloat16* __restrict__ Qlo,
              const __nv_bfloat16* __restrict__ Khi, const __nv_bfloat16* __restrict__ Klo,
              const __nv_bfloat16* __restrict__ Vhi, const __nv_bfloat16* __restrict__ Vlo,
              __nv_bfloat16* __restrict__ Yhi, __nv_bfloat16* __restrict__ Ylo)
{
    extern __shared__ __align__(128) char smA[];
    const int tid  = threadIdx.x;
    const int wid  = tid >> 5;
    const int lane = tid & 31;
    const int qt   = (int)(gridDim.x - 1) - (int)blockIdx.x;   // longest first
    const int bh   = blockIdx.y;
    const int b    = bh >> 4;
    const int h    = bh & 15;
    const int q0   = qt * 64;

    const size_t bho = (size_t)bh * TT * DD;
    const __nv_bfloat16* qh = Qhi + bho;
    const __nv_bfloat16* ql = Qlo + bho;
    const __nv_bfloat16* kh = Khi + bho;
    const __nv_bfloat16* kl = Klo + bho;
    const __nv_bfloat16* vh = Vhi + bho;
    const __nv_bfloat16* vl = Vlo + bho;

    const uint32_t smb = smem_u32(smA);

    // ---- async stage issue: 4 tiles x 4 chunks/thread ---------------------
    auto issue_stage = [&](int buf, int k0) {
        const uint32_t sb = smb + buf * ASTAGE_B;
#pragma unroll
        for (int i = 0; i < 4; i++) {
            const int c = tid + i * 128;     // 0..511
            const int r = c >> 3, col = c & 7;
            const uint32_t doff = r * ASTRB + col * 16;
            const size_t goff = (size_t)(k0 + r) * DD + col * 8;
            cpa16(sb + 0 * ATILE_B + doff, kh + goff);
            cpa16(sb + 1 * ATILE_B + doff, kl + goff);
            cpa16(sb + 2 * ATILE_B + doff, vh + goff);
            cpa16(sb + 3 * ATILE_B + doff, vl + goff);
        }
        CP_COMMIT();
    };

    // ---- Q stage (group A), then K/V stage 0 (group B) --------------------
    {
        const uint32_t sb = smb + AQ_OFF;
#pragma unroll
        for (int i = 0; i < 4; i++) {
            const int c = tid + i * 128;
            const int r = c >> 3, col = c & 7;
            const uint32_t doff = r * ASTRB + col * 16;
            const size_t goff = (size_t)(q0 + r) * DD + col * 8;
            cpa16(sb + 0 * ATILE_B + doff, qh + goff);
            cpa16(sb + 1 * ATILE_B + doff, ql + goff);
        }
        CP_COMMIT();
    }
    issue_stage(0, 0);
    CP_WAIT(1);                 // Q ready; stage0 may still fly
    __syncthreads();

    // ---- load persistent Q fragments --------------------------------------
    const int l7  = lane & 7;
    const int l8  = (lane >> 3) & 1;
    const int l16 = lane >> 4;
    uint32_t qfh[4][4], qfl[4][4];
    {
        const uint32_t qrow = wid * 16 + l7 + l8 * 8;
#pragma unroll
        for (int kc = 0; kc < 4; kc++) {
            const uint32_t off = qrow * ASTRB + kc * 32 + l16 * 16;
            ldsm4(qfh[kc][0], qfh[kc][1], qfh[kc][2], qfh[kc][3],
                  smb + AQ_OFF + off);
            ldsm4(qfl[kc][0], qfl[kc][1], qfl[kc][2], qfl[kc][3],
                  smb + AQ_OFF + ATILE_B + off);
        }
    }

    float accO[8][4];
    float mrow[2], lrow[2];
#pragma unroll
    for (int nt = 0; nt < 8; nt++)
#pragma unroll
        for (int q = 0; q < 4; q++) accO[nt][q] = 0.f;
    mrow[0] = mrow[1] = -1e30f;
    lrow[0] = lrow[1] = 0.f;

    const int rowg0 = q0 + wid * 16 + (lane >> 2);   // global q row (i=0)
    const int colg0 = (lane & 3) * 2;                // local col base

    for (int kt = 0; kt <= qt; kt++) {
        const int buf = kt & 1;
        if (kt < qt) issue_stage(buf ^ 1, (kt + 1) * 64);
        if (kt < qt) { CP_WAIT(1); } else { CP_WAIT(0); }
        __syncthreads();

        const uint32_t base = smb + buf * ASTAGE_B;

        // ---- S = Q K^T (3-term) -------------------------------------------
        float S[8][4];
#pragma unroll
        for (int nt = 0; nt < 8; nt++)
#pragma unroll
            for (int q = 0; q < 4; q++) S[nt][q] = 0.f;

        const uint32_t krow = l7 + l8 * 8;
#pragma unroll
        for (int kc = 0; kc < 4; kc++) {
#pragma unroll
            for (int p = 0; p < 4; p++) {
                const uint32_t off = (p * 16 + krow) * ASTRB + kc * 32 + l16 * 16;
                uint32_t b4h[4], b4l[4];
                ldsm4(b4h[0], b4h[1], b4h[2], b4h[3], base + 0 * ATILE_B + off);
                ldsm4(b4l[0], b4l[1], b4l[2], b4l[3], base + 1 * ATILE_B + off);
                MMA_BF16(S[2*p],   qfh[kc], b4h[0], b4h[2]);
                MMA_BF16(S[2*p],   qfh[kc], b4l[0], b4l[2]);
                MMA_BF16(S[2*p],   qfl[kc], b4h[0], b4h[2]);
                MMA_BF16(S[2*p+1], qfh[kc], b4h[1], b4h[3]);
                MMA_BF16(S[2*p+1], qfh[kc], b4l[1], b4l[3]);
                MMA_BF16(S[2*p+1], qfl[kc], b4h[1], b4h[3]);
            }
        }

        // ---- causal mask (diagonal tile) ----------------------------------
        if (kt == qt) {
            const int k0g = kt * 64;
#pragma unroll
            for (int nt = 0; nt < 8; nt++) {
                const int cg = k0g + nt * 8 + colg0;
#pragma unroll
                for (int i = 0; i < 2; i++) {
                    const int rg = rowg0 + i * 8;
                    if (cg     > rg) S[nt][2*i]     = -1e30f;
                    if (cg + 1 > rg) S[nt][2*i + 1] = -1e30f;
                }
            }
        }

        // ---- online softmax (log2 units; scale folded into Q) -------------
#pragma unroll
        for (int i = 0; i < 2; i++) {
            float mx = -1e30f;
#pragma unroll
            for (int nt = 0; nt < 8; nt++)
                mx = fmaxf(mx, fmaxf(S[nt][2*i], S[nt][2*i+1]));
            mx = fmaxf(mx, __shfl_xor_sync(0xffffffffu, mx, 1));
            mx = fmaxf(mx, __shfl_xor_sync(0xffffffffu, mx, 2));
            const float mn = fmaxf(mrow[i], mx);
            const float fac = ex2f(mrow[i] - mn);
            float rs = 0.f;
#pragma unroll
            for (int nt = 0; nt < 8; nt++) {
                float p0 = ex2f(S[nt][2*i]   - mn);
                float p1 = ex2f(S[nt][2*i+1] - mn);
                S[nt][2*i] = p0; S[nt][2*i+1] = p1;
                rs += p0 + p1;
            }
            rs += __shfl_xor_sync(0xffffffffu, rs, 1);
            rs += __shfl_xor_sync(0xffffffffu, rs, 2);
            lrow[i] = lrow[i] * fac + rs;
            mrow[i] = mn;
#pragma unroll
            for (int nt = 0; nt < 8; nt++) {
                accO[nt][2*i]   *= fac;
                accO[nt][2*i+1] *= fac;
            }
        }

        // ---- O += P V (3-term), P packed in-register ----------------------
#pragma unroll
        for (int kc = 0; kc < 4; kc++) {
            uint32_t pah[4], pal[4];
            split2(S[2*kc][0],   S[2*kc][1],   pah[0], pal[0]);
            split2(S[2*kc][2],   S[2*kc][3],   pah[1], pal[1]);
            split2(S[2*kc+1][0], S[2*kc+1][1], pah[2], pal[2]);
            split2(S[2*kc+1][2], S[2*kc+1][3], pah[3], pal[3]);
#pragma unroll
            for (int p = 0; p < 4; p++) {
                const uint32_t off = (kc * 16 + krow) * ASTRB + p * 32 + l16 * 16;
                uint32_t v4h[4], v4l[4];
                ldsm4t(v4h[0], v4h[1], v4h[2], v4h[3], base + 2 * ATILE_B + off);
                ldsm4t(v4l[0], v4l[1], v4l[2], v4l[3], base + 3 * ATILE_B + off);
                MMA_BF16(accO[2*p],   pah, v4h[0], v4h[1]);
                MMA_BF16(accO[2*p],   pah, v4l[0], v4l[1]);
                MMA_BF16(accO[2*p],   pal, v4h[0], v4h[1]);
                MMA_BF16(accO[2*p+1], pah, v4h[2], v4h[3]);
                MMA_BF16(accO[2*p+1], pah, v4l[2], v4l[3]);
                MMA_BF16(accO[2*p+1], pal, v4h[2], v4h[3]);
            }
        }
        __syncthreads();
    }

    // ---- epilogue: y[b,t,h*64+d] split bf16 -------------------------------
    const float inv0 = 1.0f / lrow[0];
    const float inv1 = 1.0f / lrow[1];
#pragma unroll
    for (int i = 0; i < 2; i++) {
        const float inv = i ? inv1 : inv0;
        const int t = rowg0 - q0 + q0 + i * 8;     // rowg0 + 8i
#pragma unroll
        for (int nt = 0; nt < 8; nt++) {
            const int d = nt * 8 + colg0;
            const size_t off = ((size_t)(b * TT + (rowg0 + i * 8))) * CC + h * DD + d;
            uint32_t hh, ll;
            split2(accO[nt][2*i] * inv, accO[nt][2*i+1] * inv, hh, ll);
            *(uint32_t*)(Yhi + off) = hh;
            *(uint32_t*)(Ylo + off) = ll;
        }
        (void)t;
    }
}

// ---------------------------------------------------------------------------
// launch
// ---------------------------------------------------------------------------
extern "C" void kernel_launch(void* const* d_in, const int* in_sizes, int n_in,
                              void* d_out, int out_size)
{
    const float* x_q = (const float*)d_in[0];
    const float* w_q = (const float*)d_in[1];
    const float* w_k = (const float*)d_in[2];
    const float* w_v = (const float*)d_in[3];
    const float* w_o = (const float*)d_in[4];
    float* out = (float*)d_out;

    __nv_bfloat16 *qhi, *qlo, *khi, *klo, *vhi, *vlo;
    cudaGetSymbolAddress((void**)&qhi, g_qhi); cudaGetSymbolAddress((void**)&qlo, g_qlo);
    cudaGetSymbolAddress((void**)&khi, g_khi); cudaGetSymbolAddress((void**)&klo, g_klo);
    cudaGetSymbolAddress((void**)&vhi, g_vhi); cudaGetSymbolAddress((void**)&vlo, g_vlo);
    __nv_bfloat16 *xhi, *xlo, *yhi, *ylo;
    __nv_bfloat16 *wqhi, *wqlo, *wkhi, *wklo, *wvhi, *wvlo, *wohi, *wolo;
    cudaGetSymbolAddress((void**)&xhi, g_xhi);  cudaGetSymbolAddress((void**)&xlo, g_xlo);
    cudaGetSymbolAddress((void**)&yhi, g_yhi);  cudaGetSymbolAddress((void**)&ylo, g_ylo);
    cudaGetSymbolAddress((void**)&wqhi, g_wqhi); cudaGetSymbolAddress((void**)&wqlo, g_wqlo);
    cudaGetSymbolAddress((void**)&wkhi, g_wkhi); cudaGetSymbolAddress((void**)&wklo, g_wklo);
    cudaGetSymbolAddress((void**)&wvhi, g_wvhi); cudaGetSymbolAddress((void**)&wvlo, g_wvlo);
    cudaGetSymbolAddress((void**)&wohi, g_wohi); cudaGetSymbolAddress((void**)&wolo, g_wolo);

    const int smemG = 2 * STAGE_B;   // 81920
    cudaFuncSetAttribute(hmma_gemm<true>,  cudaFuncAttributeMaxDynamicSharedMemorySize, smemG);
    cudaFuncSetAttribute(hmma_gemm<false>, cudaFuncAttributeMaxDynamicSharedMemorySize, smemG);
    cudaFuncSetAttribute(attn_mma, cudaFuncAttributeMaxDynamicSharedMemorySize, ASMEM_TOTAL);

    // splits
    split_kernel<<<(MROWS * KDIM / 4 + 255) / 256, 256>>>(x_q, xhi, xlo, MROWS * KDIM);
    split_kernel<<<(NDIM * KDIM / 4 + 255) / 256, 256>>>(w_q, wqhi, wqlo, NDIM * KDIM);
    split_kernel<<<(NDIM * KDIM / 4 + 255) / 256, 256>>>(w_k, wkhi, wklo, NDIM * KDIM);
    split_kernel<<<(NDIM * KDIM / 4 + 255) / 256, 256>>>(w_v, wvhi, wvlo, NDIM * KDIM);
    split_transpose<<<dim3(32, 32), dim3(32, 32)>>>(w_o, wohi, wolo);

    // projections: write split bf16 q/k/v; Q gets softmax scale folded in
    const float QSC = 0.125f * 1.44269504088896341f;
    dim3 gridG(MROWS / 128, NDIM / 128);
    hmma_gemm<true><<<gridG, 256, smemG>>>(xhi, xlo, wqhi, wqlo, nullptr, qhi, qlo, QSC);
    hmma_gemm<true><<<gridG, 256, smemG>>>(xhi, xlo, wkhi, wklo, nullptr, khi, klo, 1.0f);
    hmma_gemm<true><<<gridG, 256, smemG>>>(xhi, xlo, wvhi, wvlo, nullptr, vhi, vlo, 1.0f);

    // attention (HMMA)
    dim3 gridA(TT / 64, BB * HH);
    attn_mma<<<gridA, 128, ASMEM_TOTAL>>>(qhi, qlo, khi, klo, vhi, vlo, yhi, ylo);

    // output projection
    hmma_gemm<false><<<gridG, 256, smemG>>>(yhi, ylo, wohi, wolo, out, nullptr, nullptr, 1.0f);
}

// round 10
// speedup vs baseline: 2.0405x; 1.2532x over previous
#include <cuda_runtime.h>
#include <cuda_bf16.h>
#include <cstdint>

// ---------------------------------------------------------------------------
// Problem: B=4, T=2048, C=1024, H=16, D=64.  out = attn(xWq, xWk, xWv) Wo
// All GEMMs + attention on HMMA (mma.sync bf16, 3-term hi/lo split).
// GEMMs: cp.async staged, 2 CTAs/SM, QKV fused into one launch.
// ---------------------------------------------------------------------------
#define BB   4
#define TT   2048
#define CC   1024
#define HH   16
#define DD   64
#define MROWS (BB*TT)          // 8192
#define KDIM 1024
#define NDIM 1024
#define KOFF ((size_t)BB*HH*TT*DD)     // per-matrix q/k/v span

// ---- scratch ---------------------------------------------------------------
__device__ __nv_bfloat16 g_qkvhi[3*BB*HH*TT*DD], g_qkvlo[3*BB*HH*TT*DD];
__device__ __nv_bfloat16 g_xhi[MROWS*KDIM], g_xlo[MROWS*KDIM];
__device__ __nv_bfloat16 g_yhi[MROWS*KDIM], g_ylo[MROWS*KDIM];
__device__ __nv_bfloat16 g_wallhi[3*NDIM*KDIM], g_walllo[3*NDIM*KDIM];
__device__ __nv_bfloat16 g_wohi[NDIM*KDIM], g_wolo[NDIM*KDIM];

__device__ __forceinline__ uint32_t smem_u32(const void* p) {
    uint32_t a;
    asm("{ .reg .u64 t; cvta.to.shared.u64 t, %1; cvt.u32.u64 %0, t; }"
        : "=r"(a) : "l"(p));
    return a;
}
__device__ __forceinline__ void ldsm4(uint32_t& r0, uint32_t& r1,
                                      uint32_t& r2, uint32_t& r3, uint32_t addr) {
    asm volatile("ldmatrix.sync.aligned.m8n8.x4.shared.b16 {%0,%1,%2,%3}, [%4];"
                 : "=r"(r0), "=r"(r1), "=r"(r2), "=r"(r3) : "r"(addr));
}
__device__ __forceinline__ void ldsm4t(uint32_t& r0, uint32_t& r1,
                                       uint32_t& r2, uint32_t& r3, uint32_t addr) {
    asm volatile("ldmatrix.sync.aligned.m8n8.x4.trans.shared.b16 {%0,%1,%2,%3}, [%4];"
                 : "=r"(r0), "=r"(r1), "=r"(r2), "=r"(r3) : "r"(addr));
}
#define MMA_BF16(d, a, b0, b1)                                              \
    asm volatile("mma.sync.aligned.m16n8k16.row.col.f32.bf16.bf16.f32 "     \
                 "{%0,%1,%2,%3}, {%4,%5,%6,%7}, {%8,%9}, {%0,%1,%2,%3};"    \
                 : "+f"((d)[0]), "+f"((d)[1]), "+f"((d)[2]), "+f"((d)[3])   \
                 : "r"((a)[0]), "r"((a)[1]), "r"((a)[2]), "r"((a)[3]),      \
                   "r"(b0), "r"(b1))
__device__ __forceinline__ void cpa16(uint32_t dst, const void* src) {
    asm volatile("cp.async.cg.shared.global [%0], [%1], 16;"
                 :: "r"(dst), "l"(src));
}
#define CP_COMMIT() asm volatile("cp.async.commit_group;")
#define CP_WAIT(n)  asm volatile("cp.async.wait_group %0;" :: "n"(n))
__device__ __forceinline__ float ex2f(float x) {
    float y; asm("ex2.approx.ftz.f32 %0, %1;" : "=f"(y) : "f"(x)); return y;
}
__device__ __forceinline__ void split2(float a, float b, uint32_t& hi, uint32_t& lo) {
    __nv_bfloat16 ha = __float2bfloat16_rn(a), hb = __float2bfloat16_rn(b);
    __nv_bfloat16 la = __float2bfloat16_rn(a - __bfloat162float(ha));
    __nv_bfloat16 lb = __float2bfloat16_rn(b - __bfloat162float(hb));
    __nv_bfloat162 vh = __halves2bfloat162(ha, hb), vl = __halves2bfloat162(la, lb);
    hi = *(uint32_t*)&vh; lo = *(uint32_t*)&vl;
}

// ---------------------------------------------------------------------------
// split kernels
// ---------------------------------------------------------------------------
__global__ void split_kernel(const float* __restrict__ src,
                             __nv_bfloat16* __restrict__ hi,
                             __nv_bfloat16* __restrict__ lo, int n)
{
    int i = (blockIdx.x * blockDim.x + threadIdx.x) * 4;
    if (i >= n) return;
    float4 v = *(const float4*)(src + i);
    float xs[4] = {v.x, v.y, v.z, v.w};
    __nv_bfloat16 hs[4], ls[4];
#pragma unroll
    for (int j = 0; j < 4; j++) {
        hs[j] = __float2bfloat16_rn(xs[j]);
        ls[j] = __float2bfloat16_rn(xs[j] - __bfloat162float(hs[j]));
    }
    *(__nv_bfloat162*)(hi + i)     = __halves2bfloat162(hs[0], hs[1]);
    *(__nv_bfloat162*)(hi + i + 2) = __halves2bfloat162(hs[2], hs[3]);
    *(__nv_bfloat162*)(lo + i)     = __halves2bfloat162(ls[0], ls[1]);
    *(__nv_bfloat162*)(lo + i + 2) = __halves2bfloat162(ls[2], ls[3]);
}

// three weight matrices in one launch; out = wall + mat*N*K
__global__ void split_w3(const float* __restrict__ w0, const float* __restrict__ w1,
                         const float* __restrict__ w2,
                         __nv_bfloat16* __restrict__ hi, __nv_bfloat16* __restrict__ lo)
{
    const int mat = blockIdx.y;
    const float* src = (mat == 0) ? w0 : (mat == 1) ? w1 : w2;
    const size_t base = (size_t)mat * NDIM * KDIM;
    int i = (blockIdx.x * blockDim.x + threadIdx.x) * 4;
    float4 v = *(const float4*)(src + i);
    float xs[4] = {v.x, v.y, v.z, v.w};
    __nv_bfloat16 hs[4], ls[4];
#pragma unroll
    for (int j = 0; j < 4; j++) {
        hs[j] = __float2bfloat16_rn(xs[j]);
        ls[j] = __float2bfloat16_rn(xs[j] - __bfloat162float(hs[j]));
    }
    *(__nv_bfloat162*)(hi + base + i)     = __halves2bfloat162(hs[0], hs[1]);
    *(__nv_bfloat162*)(hi + base + i + 2) = __halves2bfloat162(hs[2], hs[3]);
    *(__nv_bfloat162*)(lo + base + i)     = __halves2bfloat162(ls[0], ls[1]);
    *(__nv_bfloat162*)(lo + base + i + 2) = __halves2bfloat162(ls[2], ls[3]);
}

__global__ void split_transpose(const float* __restrict__ W,
                                __nv_bfloat16* __restrict__ hi,
                                __nv_bfloat16* __restrict__ lo)
{
    __shared__ float tile[32][33];
    const int n0 = blockIdx.x * 32, k0 = blockIdx.y * 32;
    const int tx = threadIdx.x, ty = threadIdx.y;
    tile[ty][tx] = W[(k0 + ty) * NDIM + n0 + tx];
    __syncthreads();
    float v = tile[tx][ty];
    __nv_bfloat16 h = __float2bfloat16_rn(v);
    __nv_bfloat16 l = __float2bfloat16_rn(v - __bfloat162float(h));
    const int o = (n0 + ty) * KDIM + k0 + tx;
    hi[o] = h;
    lo[o] = l;
}

// ---------------------------------------------------------------------------
// HMMA GEMM, cp.async staged, 2 CTAs/SM target.
//   QKV=true : grid (64, 24); blockIdx.y selects matrix (y>>3) and n-tile;
//              split-bf16 scatter epilogue, Q pre-scaled by 0.125*log2e.
//   QKV=false: grid (64, 8); fp32 row-major epilogue.
// A [M,K] bf16 hi/lo; B [N,K] bf16 hi/lo (per-matrix stride N*K).
// ---------------------------------------------------------------------------
#define S_ROWB   80
#define TILE_B   (128 * S_ROWB)           // 10240
#define STAGE_B  (4 * TILE_B)             // 40960

template <bool QKV>
__global__ __launch_bounds__(256, 2)
void hmma_gemm(const __nv_bfloat16* __restrict__ Ahi, const __nv_bfloat16* __restrict__ Alo,
               const __nv_bfloat16* __restrict__ BhiAll, const __nv_bfloat16* __restrict__ BloAll,
               float* __restrict__ C,
               __nv_bfloat16* __restrict__ Chi, __nv_bfloat16* __restrict__ Clo)
{
    extern __shared__ __align__(128) char sm[];
    const int tid  = threadIdx.x;
    const int wid  = tid >> 5;
    const int lane = tid & 31;
    const int m0   = blockIdx.x * 128;
    const int mat  = QKV ? (blockIdx.y >> 3) : 0;
    const int n0   = (QKV ? (blockIdx.y & 7) : blockIdx.y) * 128;

    const __nv_bfloat16* Bhi = BhiAll + (size_t)mat * NDIM * KDIM;
    const __nv_bfloat16* Blo = BloAll + (size_t)mat * NDIM * KDIM;
    const float preScale = (QKV && mat == 0) ? (0.125f * 1.44269504088896341f) : 1.0f;

    const int wm0 = (wid & 3) * 32;
    const int wn0 = (wid >> 2) * 64;

    // ---- cp.async staging: 512 16B-chunks/tile, threads cover 2 each -----
    const int r0c = tid >> 2, c0c = tid & 3;          // rows 0..63
    const int r1c = r0c + 64;                          // rows 64..127
    const size_t ga0 = (size_t)(m0 + r0c) * KDIM + c0c * 8;
    const size_t ga1 = (size_t)(m0 + r1c) * KDIM + c0c * 8;
    const size_t gb0 = (size_t)(n0 + r0c) * KDIM + c0c * 8;
    const size_t gb1 = (size_t)(n0 + r1c) * KDIM + c0c * 8;
    const uint32_t smb = smem_u32(sm);
    const uint32_t s0 = r0c * S_ROWB + c0c * 16;
    const uint32_t s1 = r1c * S_ROWB + c0c * 16;

    auto issue = [&](int st, int kt) {
        const int kc = kt * 32;
        const uint32_t bb = smb + st * STAGE_B;
        cpa16(bb + 0 * TILE_B + s0, Ahi + ga0 + kc);
        cpa16(bb + 0 * TILE_B + s1, Ahi + ga1 + kc);
        cpa16(bb + 1 * TILE_B + s0, Alo + ga0 + kc);
        cpa16(bb + 1 * TILE_B + s1, Alo + ga1 + kc);
        cpa16(bb + 2 * TILE_B + s0, Bhi + gb0 + kc);
        cpa16(bb + 2 * TILE_B + s1, Bhi + gb1 + kc);
        cpa16(bb + 3 * TILE_B + s0, Blo + gb0 + kc);
        cpa16(bb + 3 * TILE_B + s1, Blo + gb1 + kc);
        CP_COMMIT();
    };

    // ---- ldmatrix addressing ---------------------------------------------
    const uint32_t aRow = wm0 + (lane & 15);
    const uint32_t aChunkBase = (lane >> 4);
    const uint32_t g = lane >> 3;
    const uint32_t bRow = wn0 + (lane & 7) + ((g >> 1) << 3);
    const uint32_t bChunkBase = (g & 1);

    float acc[2][8][4];
#pragma unroll
    for (int i = 0; i < 2; i++)
#pragma unroll
        for (int j = 0; j < 8; j++)
#pragma unroll
            for (int q = 0; q < 4; q++) acc[i][j][q] = 0.f;

    issue(0, 0);

    for (int kt = 0; kt < 32; kt++) {
        const int st = kt & 1;
        if (kt < 31) { issue(st ^ 1, kt + 1); CP_WAIT(1); }
        else         { CP_WAIT(0); }
        __syncthreads();

        const uint32_t base = smb + st * STAGE_B;
#pragma unroll
        for (int ksub = 0; ksub < 2; ksub++) {
            uint32_t ahi[2][4], alo[2][4];
#pragma unroll
            for (int mi = 0; mi < 2; mi++) {
                const uint32_t off = (aRow + mi * 16) * S_ROWB
                                   + (ksub * 2 + aChunkBase) * 16;
                ldsm4(ahi[mi][0], ahi[mi][1], ahi[mi][2], ahi[mi][3],
                      base + 0 * TILE_B + off);
                ldsm4(alo[mi][0], alo[mi][1], alo[mi][2], alo[mi][3],
                      base + 1 * TILE_B + off);
            }
#pragma unroll
            for (int pj = 0; pj < 4; pj++) {
                const uint32_t off = (bRow + pj * 16) * S_ROWB
                                   + (ksub * 2 + bChunkBase) * 16;
                uint32_t bh[4], bl[4];
                ldsm4(bh[0], bh[1], bh[2], bh[3], base + 2 * TILE_B + off);
                ldsm4(bl[0], bl[1], bl[2], bl[3], base + 3 * TILE_B + off);
#pragma unroll
                for (int mi = 0; mi < 2; mi++) {
                    MMA_BF16(acc[mi][2*pj],   ahi[mi], bh[0], bh[1]);
                    MMA_BF16(acc[mi][2*pj],   ahi[mi], bl[0], bl[1]);
                    MMA_BF16(acc[mi][2*pj],   alo[mi], bh[0], bh[1]);
                    MMA_BF16(acc[mi][2*pj+1], ahi[mi], bh[2], bh[3]);
                    MMA_BF16(acc[mi][2*pj+1], ahi[mi], bl[2], bl[3]);
                    MMA_BF16(acc[mi][2*pj+1], alo[mi], bh[2], bh[3]);
                }
            }
        }
        __syncthreads();
    }

    // ---- epilogue ---------------------------------------------------------
#pragma unroll
    for (int mi = 0; mi < 2; mi++) {
#pragma unroll
        for (int nt = 0; nt < 8; nt++) {
            const int mrow0 = m0 + wm0 + mi * 16 + (lane >> 2);
            const int ncol  = n0 + wn0 + nt * 8 + (lane & 3) * 2;
            if (QKV) {
                const int h = ncol >> 6, d = ncol & 63;
#pragma unroll
                for (int half = 0; half < 2; half++) {
                    const int m = mrow0 + half * 8;
                    const int b = m >> 11, t = m & 2047;
                    const size_t off = (size_t)mat * KOFF
                                     + (((size_t)(b * HH + h) * TT + t) * DD + d);
                    uint32_t hh, ll;
                    split2(acc[mi][nt][half * 2] * preScale,
                           acc[mi][nt][half * 2 + 1] * preScale, hh, ll);
                    *(uint32_t*)(Chi + off) = hh;
                    *(uint32_t*)(Clo + off) = ll;
                }
            } else {
#pragma unroll
                for (int half = 0; half < 2; half++) {
                    float* o = C + (size_t)(mrow0 + half * 8) * NDIM + ncol;
                    *(float2*)o = make_float2(acc[mi][nt][half * 2],
                                              acc[mi][nt][half * 2 + 1]);
                }
            }
        }
    }
}

// ---------------------------------------------------------------------------
// HMMA flash attention (unchanged from R9, fused q/k/v arrays).
// ---------------------------------------------------------------------------
#define ASTRB   144
#define ATILE_B (64 * ASTRB)               // 9216
#define ASTAGE_B (4 * ATILE_B)             // 36864
#define AQ_OFF  (2 * ASTAGE_B)
#define ASMEM_TOTAL (AQ_OFF + 2 * ATILE_B) // 92160

__global__ __launch_bounds__(128)
void attn_mma(const __nv_bfloat16* __restrict__ QKVhi,
              const __nv_bfloat16* __restrict__ QKVlo,
              __nv_bfloat16* __restrict__ Yhi, __nv_bfloat16* __restrict__ Ylo)
{
    extern __shared__ __align__(128) char smA[];
    const int tid  = threadIdx.x;
    const int wid  = tid >> 5;
    const int lane = tid & 31;
    const int qt   = (int)(gridDim.x - 1) - (int)blockIdx.x;
    const int bh   = blockIdx.y;
    const int b    = bh >> 4;
    const int h    = bh & 15;
    const int q0   = qt * 64;

    const size_t bho = (size_t)bh * TT * DD;
    const __nv_bfloat16* qh = QKVhi + bho;
    const __nv_bfloat16* ql = QKVlo + bho;
    const __nv_bfloat16* kh = QKVhi + KOFF + bho;
    const __nv_bfloat16* kl = QKVlo + KOFF + bho;
    const __nv_bfloat16* vh = QKVhi + 2 * KOFF + bho;
    const __nv_bfloat16* vl = QKVlo + 2 * KOFF + bho;

    const uint32_t smb = smem_u32(smA);

    auto issue_stage = [&](int buf, int k0) {
        const uint32_t sb = smb + buf * ASTAGE_B;
#pragma unroll
        for (int i = 0; i < 4; i++) {
            const int c = tid + i * 128;
            const int r = c >> 3, col = c & 7;
            const uint32_t doff = r * ASTRB + col * 16;
            const size_t goff = (size_t)(k0 + r) * DD + col * 8;
            cpa16(sb + 0 * ATILE_B + doff, kh + goff);
            cpa16(sb + 1 * ATILE_B + doff, kl + goff);
            cpa16(sb + 2 * ATILE_B + doff, vh + goff);
            cpa16(sb + 3 * ATILE_B + doff, vl + goff);
        }
        CP_COMMIT();
    };

    {
        const uint32_t sb = smb + AQ_OFF;
#pragma unroll
        for (int i = 0; i < 4; i++) {
            const int c = tid + i * 128;
            const int r = c >> 3, col = c & 7;
            const uint32_t doff = r * ASTRB + col * 16;
            const size_t goff = (size_t)(q0 + r) * DD + col * 8;
            cpa16(sb + 0 * ATILE_B + doff, qh + goff);
            cpa16(sb + 1 * ATILE_B + doff, ql + goff);
        }
        CP_COMMIT();
    }
    issue_stage(0, 0);
    CP_WAIT(1);
    __syncthreads();

    const int l7  = lane & 7;
    const int l8  = (lane >> 3) & 1;
    const int l16 = lane >> 4;
    uint32_t qfh[4][4], qfl[4][4];
    {
        const uint32_t qrow = wid * 16 + l7 + l8 * 8;
#pragma unroll
        for (int kc = 0; kc < 4; kc++) {
            const uint32_t off = qrow * ASTRB + kc * 32 + l16 * 16;
            ldsm4(qfh[kc][0], qfh[kc][1], qfh[kc][2], qfh[kc][3],
                  smb + AQ_OFF + off);
            ldsm4(qfl[kc][0], qfl[kc][1], qfl[kc][2], qfl[kc][3],
                  smb + AQ_OFF + ATILE_B + off);
        }
    }

    float accO[8][4];
    float mrow[2], lrow[2];
#pragma unroll
    for (int nt = 0; nt < 8; nt++)
#pragma unroll
        for (int q = 0; q < 4; q++) accO[nt][q] = 0.f;
    mrow[0] = mrow[1] = -1e30f;
    lrow[0] = lrow[1] = 0.f;

    const int rowg0 = q0 + wid * 16 + (lane >> 2);
    const int colg0 = (lane & 3) * 2;

    for (int kt = 0; kt <= qt; kt++) {
        const int buf = kt & 1;
        if (kt < qt) { issue_stage(buf ^ 1, (kt + 1) * 64); CP_WAIT(1); }
        else         { CP_WAIT(0); }
        __syncthreads();

        const uint32_t base = smb + buf * ASTAGE_B;

        float S[8][4];
#pragma unroll
        for (int nt = 0; nt < 8; nt++)
#pragma unroll
            for (int q = 0; q < 4; q++) S[nt][q] = 0.f;

        const uint32_t krow = l7 + l8 * 8;
#pragma unroll
        for (int kc = 0; kc < 4; kc++) {
#pragma unroll
            for (int p = 0; p < 4; p++) {
                const uint32_t off = (p * 16 + krow) * ASTRB + kc * 32 + l16 * 16;
                uint32_t b4h[4], b4l[4];
                ldsm4(b4h[0], b4h[1], b4h[2], b4h[3], base + 0 * ATILE_B + off);
                ldsm4(b4l[0], b4l[1], b4l[2], b4l[3], base + 1 * ATILE_B + off);
                MMA_BF16(S[2*p],   qfh[kc], b4h[0], b4h[2]);
                MMA_BF16(S[2*p],   qfh[kc], b4l[0], b4l[2]);
                MMA_BF16(S[2*p],   qfl[kc], b4h[0], b4h[2]);
                MMA_BF16(S[2*p+1], qfh[kc], b4h[1], b4h[3]);
                MMA_BF16(S[2*p+1], qfh[kc], b4l[1], b4l[3]);
                MMA_BF16(S[2*p+1], qfl[kc], b4h[1], b4h[3]);
            }
        }

        if (kt == qt) {
            const int k0g = kt * 64;
#pragma unroll
            for (int nt = 0; nt < 8; nt++) {
                const int cg = k0g + nt * 8 + colg0;
#pragma unroll
                for (int i = 0; i < 2; i++) {
                    const int rg = rowg0 + i * 8;
                    if (cg     > rg) S[nt][2*i]     = -1e30f;
                    if (cg + 1 > rg) S[nt][2*i + 1] = -1e30f;
                }
            }
        }

#pragma unroll
        for (int i = 0; i < 2; i++) {
            float mx = -1e30f;
#pragma unroll
            for (int nt = 0; nt < 8; nt++)
                mx = fmaxf(mx, fmaxf(S[nt][2*i], S[nt][2*i+1]));
            mx = fmaxf(mx, __shfl_xor_sync(0xffffffffu, mx, 1));
            mx = fmaxf(mx, __shfl_xor_sync(0xffffffffu, mx, 2));
            const float mn = fmaxf(mrow[i], mx);
            const float fac = ex2f(mrow[i] - mn);
            float rs = 0.f;
#pragma unroll
            for (int nt = 0; nt < 8; nt++) {
                float p0 = ex2f(S[nt][2*i]   - mn);
                float p1 = ex2f(S[nt][2*i+1] - mn);
                S[nt][2*i] = p0; S[nt][2*i+1] = p1;
                rs += p0 + p1;
            }
            rs += __shfl_xor_sync(0xffffffffu, rs, 1);
            rs += __shfl_xor_sync(0xffffffffu, rs, 2);
            lrow[i] = lrow[i] * fac + rs;
            mrow[i] = mn;
#pragma unroll
            for (int nt = 0; nt < 8; nt++) {
                accO[nt][2*i]   *= fac;
                accO[nt][2*i+1] *= fac;
            }
        }

#pragma unroll
        for (int kc = 0; kc < 4; kc++) {
            uint32_t pah[4], pal[4];
            split2(S[2*kc][0],   S[2*kc][1],   pah[0], pal[0]);
            split2(S[2*kc][2],   S[2*kc][3],   pah[1], pal[1]);
            split2(S[2*kc+1][0], S[2*kc+1][1], pah[2], pal[2]);
            split2(S[2*kc+1][2], S[2*kc+1][3], pah[3], pal[3]);
#pragma unroll
            for (int p = 0; p < 4; p++) {
                const uint32_t off = (kc * 16 + krow) * ASTRB + p * 32 + l16 * 16;
                uint32_t v4h[4], v4l[4];
                ldsm4t(v4h[0], v4h[1], v4h[2], v4h[3], base + 2 * ATILE_B + off);
                ldsm4t(v4l[0], v4l[1], v4l[2], v4l[3], base + 3 * ATILE_B + off);
                MMA_BF16(accO[2*p],   pah, v4h[0], v4h[1]);
                MMA_BF16(accO[2*p],   pah, v4l[0], v4l[1]);
                MMA_BF16(accO[2*p],   pal, v4h[0], v4h[1]);
                MMA_BF16(accO[2*p+1], pah, v4h[2], v4h[3]);
                MMA_BF16(accO[2*p+1], pah, v4l[2], v4l[3]);
                MMA_BF16(accO[2*p+1], pal, v4h[2], v4h[3]);
            }
        }
        __syncthreads();
    }

    const float inv0 = 1.0f / lrow[0];
    const float inv1 = 1.0f / lrow[1];
#pragma unroll
    for (int i = 0; i < 2; i++) {
        const float inv = i ? inv1 : inv0;
#pragma unroll
        for (int nt = 0; nt < 8; nt++) {
            const int d = nt * 8 + colg0;
            const size_t off = ((size_t)(b * TT + (rowg0 + i * 8))) * CC + h * DD + d;
            uint32_t hh, ll;
            split2(accO[nt][2*i] * inv, accO[nt][2*i+1] * inv, hh, ll);
            *(uint32_t*)(Yhi + off) = hh;
            *(uint32_t*)(Ylo + off) = ll;
        }
    }
}

// ---------------------------------------------------------------------------
// launch
// ---------------------------------------------------------------------------
extern "C" void kernel_launch(void* const* d_in, const int* in_sizes, int n_in,
                              void* d_out, int out_size)
{
    const float* x_q = (const float*)d_in[0];
    const float* w_q = (const float*)d_in[1];
    const float* w_k = (const float*)d_in[2];
    const float* w_v = (const float*)d_in[3];
    const float* w_o = (const float*)d_in[4];
    float* out = (float*)d_out;

    __nv_bfloat16 *qkvhi, *qkvlo, *xhi, *xlo, *yhi, *ylo;
    __nv_bfloat16 *wallhi, *walllo, *wohi, *wolo;
    cudaGetSymbolAddress((void**)&qkvhi, g_qkvhi);
    cudaGetSymbolAddress((void**)&qkvlo, g_qkvlo);
    cudaGetSymbolAddress((void**)&xhi, g_xhi);   cudaGetSymbolAddress((void**)&xlo, g_xlo);
    cudaGetSymbolAddress((void**)&yhi, g_yhi);   cudaGetSymbolAddress((void**)&ylo, g_ylo);
    cudaGetSymbolAddress((void**)&wallhi, g_wallhi);
    cudaGetSymbolAddress((void**)&walllo, g_walllo);
    cudaGetSymbolAddress((void**)&wohi, g_wohi); cudaGetSymbolAddress((void**)&wolo, g_wolo);

    const int smemG = 2 * STAGE_B;   // 81920
    cudaFuncSetAttribute(hmma_gemm<true>,  cudaFuncAttributeMaxDynamicSharedMemorySize, smemG);
    cudaFuncSetAttribute(hmma_gemm<false>, cudaFuncAttributeMaxDynamicSharedMemorySize, smemG);
    cudaFuncSetAttribute(attn_mma, cudaFuncAttributeMaxDynamicSharedMemorySize, ASMEM_TOTAL);

    // splits
    split_kernel<<<(MROWS * KDIM / 4 + 255) / 256, 256>>>(x_q, xhi, xlo, MROWS * KDIM);
    split_w3<<<dim3(NDIM * KDIM / 4 / 256, 3), 256>>>(w_q, w_k, w_v, wallhi, walllo);
    split_transpose<<<dim3(32, 32), dim3(32, 32)>>>(w_o, wohi, wolo);

    // fused QKV projection
    dim3 gridQKV(MROWS / 128, 24);
    hmma_gemm<true><<<gridQKV, 256, smemG>>>(xhi, xlo, wallhi, walllo,
                                             nullptr, qkvhi, qkvlo);

    // attention
    dim3 gridA(TT / 64, BB * HH);
    attn_mma<<<gridA, 128, ASMEM_TOTAL>>>(qkvhi, qkvlo, yhi, ylo);

    // output projection
    dim3 gridO(MROWS / 128, NDIM / 128);
    hmma_gemm<false><<<gridO, 256, smemG>>>(yhi, ylo, wohi, wolo,
                                            out, nullptr, nullptr);
}

// round 11
// speedup vs baseline: 2.3068x; 1.1305x over previous
#include <cuda_runtime.h>
#include <cuda_bf16.h>
#include <cstdint>

// ---------------------------------------------------------------------------
// Problem: B=4, T=2048, C=1024, H=16, D=64.  out = attn(xWq, xWk, xWv) Wo
// All GEMMs + attention on HMMA (mma.sync bf16, 3-term hi/lo split).
// R11: GEMM 3-stage swizzled cp.async pipeline; attention 128-row Q tile.
// ---------------------------------------------------------------------------
#define BB   4
#define TT   2048
#define CC   1024
#define HH   16
#define DD   64
#define MROWS (BB*TT)          // 8192
#define KDIM 1024
#define NDIM 1024
#define KOFF ((size_t)BB*HH*TT*DD)     // per-matrix q/k/v span

// ---- scratch ---------------------------------------------------------------
__device__ __nv_bfloat16 g_qkvhi[3*BB*HH*TT*DD], g_qkvlo[3*BB*HH*TT*DD];
__device__ __nv_bfloat16 g_xhi[MROWS*KDIM], g_xlo[MROWS*KDIM];
__device__ __nv_bfloat16 g_yhi[MROWS*KDIM], g_ylo[MROWS*KDIM];
__device__ __nv_bfloat16 g_wallhi[3*NDIM*KDIM], g_walllo[3*NDIM*KDIM];
__device__ __nv_bfloat16 g_wohi[NDIM*KDIM], g_wolo[NDIM*KDIM];

__device__ __forceinline__ uint32_t smem_u32(const void* p) {
    uint32_t a;
    asm("{ .reg .u64 t; cvta.to.shared.u64 t, %1; cvt.u32.u64 %0, t; }"
        : "=r"(a) : "l"(p));
    return a;
}
__device__ __forceinline__ void ldsm4(uint32_t& r0, uint32_t& r1,
                                      uint32_t& r2, uint32_t& r3, uint32_t addr) {
    asm volatile("ldmatrix.sync.aligned.m8n8.x4.shared.b16 {%0,%1,%2,%3}, [%4];"
                 : "=r"(r0), "=r"(r1), "=r"(r2), "=r"(r3) : "r"(addr));
}
__device__ __forceinline__ void ldsm4t(uint32_t& r0, uint32_t& r1,
                                       uint32_t& r2, uint32_t& r3, uint32_t addr) {
    asm volatile("ldmatrix.sync.aligned.m8n8.x4.trans.shared.b16 {%0,%1,%2,%3}, [%4];"
                 : "=r"(r0), "=r"(r1), "=r"(r2), "=r"(r3) : "r"(addr));
}
#define MMA_BF16(d, a, b0, b1)                                              \
    asm volatile("mma.sync.aligned.m16n8k16.row.col.f32.bf16.bf16.f32 "     \
                 "{%0,%1,%2,%3}, {%4,%5,%6,%7}, {%8,%9}, {%0,%1,%2,%3};"    \
                 : "+f"((d)[0]), "+f"((d)[1]), "+f"((d)[2]), "+f"((d)[3])   \
                 : "r"((a)[0]), "r"((a)[1]), "r"((a)[2]), "r"((a)[3]),      \
                   "r"(b0), "r"(b1))
__device__ __forceinline__ void cpa16(uint32_t dst, const void* src) {
    asm volatile("cp.async.cg.shared.global [%0], [%1], 16;"
                 :: "r"(dst), "l"(src));
}
#define CP_COMMIT() asm volatile("cp.async.commit_group;")
#define CP_WAIT(n)  asm volatile("cp.async.wait_group %0;" :: "n"(n))
__device__ __forceinline__ float ex2f(float x) {
    float y; asm("ex2.approx.ftz.f32 %0, %1;" : "=f"(y) : "f"(x)); return y;
}
__device__ __forceinline__ void split2(float a, float b, uint32_t& hi, uint32_t& lo) {
    __nv_bfloat16 ha = __float2bfloat16_rn(a), hb = __float2bfloat16_rn(b);
    __nv_bfloat16 la = __float2bfloat16_rn(a - __bfloat162float(ha));
    __nv_bfloat16 lb = __float2bfloat16_rn(b - __bfloat162float(hb));
    __nv_bfloat162 vh = __halves2bfloat162(ha, hb), vl = __halves2bfloat162(la, lb);
    hi = *(uint32_t*)&vh; lo = *(uint32_t*)&vl;
}

// ---------------------------------------------------------------------------
// split kernels
// ---------------------------------------------------------------------------
__global__ void split_kernel(const float* __restrict__ src,
                             __nv_bfloat16* __restrict__ hi,
                             __nv_bfloat16* __restrict__ lo, int n)
{
    int i = (blockIdx.x * blockDim.x + threadIdx.x) * 4;
    if (i >= n) return;
    float4 v = *(const float4*)(src + i);
    float xs[4] = {v.x, v.y, v.z, v.w};
    __nv_bfloat16 hs[4], ls[4];
#pragma unroll
    for (int j = 0; j < 4; j++) {
        hs[j] = __float2bfloat16_rn(xs[j]);
        ls[j] = __float2bfloat16_rn(xs[j] - __bfloat162float(hs[j]));
    }
    *(__nv_bfloat162*)(hi + i)     = __halves2bfloat162(hs[0], hs[1]);
    *(__nv_bfloat162*)(hi + i + 2) = __halves2bfloat162(hs[2], hs[3]);
    *(__nv_bfloat162*)(lo + i)     = __halves2bfloat162(ls[0], ls[1]);
    *(__nv_bfloat162*)(lo + i + 2) = __halves2bfloat162(ls[2], ls[3]);
}

__global__ void split_w3(const float* __restrict__ w0, const float* __restrict__ w1,
                         const float* __restrict__ w2,
                         __nv_bfloat16* __restrict__ hi, __nv_bfloat16* __restrict__ lo)
{
    const int mat = blockIdx.y;
    const float* src = (mat == 0) ? w0 : (mat == 1) ? w1 : w2;
    const size_t base = (size_t)mat * NDIM * KDIM;
    int i = (blockIdx.x * blockDim.x + threadIdx.x) * 4;
    float4 v = *(const float4*)(src + i);
    float xs[4] = {v.x, v.y, v.z, v.w};
    __nv_bfloat16 hs[4], ls[4];
#pragma unroll
    for (int j = 0; j < 4; j++) {
        hs[j] = __float2bfloat16_rn(xs[j]);
        ls[j] = __float2bfloat16_rn(xs[j] - __bfloat162float(hs[j]));
    }
    *(__nv_bfloat162*)(hi + base + i)     = __halves2bfloat162(hs[0], hs[1]);
    *(__nv_bfloat162*)(hi + base + i + 2) = __halves2bfloat162(hs[2], hs[3]);
    *(__nv_bfloat162*)(lo + base + i)     = __halves2bfloat162(ls[0], ls[1]);
    *(__nv_bfloat162*)(lo + base + i + 2) = __halves2bfloat162(ls[2], ls[3]);
}

__global__ void split_transpose(const float* __restrict__ W,
                                __nv_bfloat16* __restrict__ hi,
                                __nv_bfloat16* __restrict__ lo)
{
    __shared__ float tile[32][33];
    const int n0 = blockIdx.x * 32, k0 = blockIdx.y * 32;
    const int tx = threadIdx.x, ty = threadIdx.y;
    tile[ty][tx] = W[(k0 + ty) * NDIM + n0 + tx];
    __syncthreads();
    float v = tile[tx][ty];
    __nv_bfloat16 h = __float2bfloat16_rn(v);
    __nv_bfloat16 l = __float2bfloat16_rn(v - __bfloat162float(h));
    const int o = (n0 + ty) * KDIM + k0 + tx;
    hi[o] = h;
    lo[o] = l;
}

// ---------------------------------------------------------------------------
// HMMA GEMM, 3-stage swizzled cp.async pipeline, 2 CTAs/SM.
// Tiles 128x128xBK32. Rows in smem: 64B, 16B-chunk swizzle c ^= (r>>1)&3.
// ---------------------------------------------------------------------------
#define TILE_B   (128 * 64)               // 8192 bytes per tile
#define STAGE_B  (4 * TILE_B)             // 32768
#define NSTG     3

template <bool QKV>
__global__ __launch_bounds__(256, 2)
void hmma_gemm(const __nv_bfloat16* __restrict__ Ahi, const __nv_bfloat16* __restrict__ Alo,
               const __nv_bfloat16* __restrict__ BhiAll, const __nv_bfloat16* __restrict__ BloAll,
               float* __restrict__ C,
               __nv_bfloat16* __restrict__ Chi, __nv_bfloat16* __restrict__ Clo)
{
    extern __shared__ __align__(128) char sm[];
    const int tid  = threadIdx.x;
    const int wid  = tid >> 5;
    const int lane = tid & 31;
    const int m0   = blockIdx.x * 128;
    const int mat  = QKV ? (blockIdx.y >> 3) : 0;
    const int n0   = (QKV ? (blockIdx.y & 7) : blockIdx.y) * 128;

    const __nv_bfloat16* Bhi = BhiAll + (size_t)mat * NDIM * KDIM;
    const __nv_bfloat16* Blo = BloAll + (size_t)mat * NDIM * KDIM;
    const float preScale = (QKV && mat == 0) ? (0.125f * 1.44269504088896341f) : 1.0f;

    const int wm0 = (wid & 3) * 32;
    const int wn0 = (wid >> 2) * 64;

    // ---- cp.async staging (swizzled) --------------------------------------
    const int r0c = tid >> 2, c0c = tid & 3;          // rows 0..63 / chunk 0..3
    const size_t ga0 = (size_t)(m0 + r0c) * KDIM + c0c * 8;
    const size_t ga1 = (size_t)(m0 + r0c + 64) * KDIM + c0c * 8;
    const size_t gb0 = (size_t)(n0 + r0c) * KDIM + c0c * 8;
    const size_t gb1 = (size_t)(n0 + r0c + 64) * KDIM + c0c * 8;
    const uint32_t smb = smem_u32(sm);
    const uint32_t s0 = r0c * 64 + ((c0c ^ ((r0c >> 1) & 3)) << 4);
    const uint32_t s1 = s0 + 64 * 64;                  // rows +64: same xor

    auto issue = [&](int st, int kt) {
        const int kc = kt * 32;
        const uint32_t bb = smb + st * STAGE_B;
        cpa16(bb + 0 * TILE_B + s0, Ahi + ga0 + kc);
        cpa16(bb + 0 * TILE_B + s1, Ahi + ga1 + kc);
        cpa16(bb + 1 * TILE_B + s0, Alo + ga0 + kc);
        cpa16(bb + 1 * TILE_B + s1, Alo + ga1 + kc);
        cpa16(bb + 2 * TILE_B + s0, Bhi + gb0 + kc);
        cpa16(bb + 2 * TILE_B + s1, Bhi + gb1 + kc);
        cpa16(bb + 3 * TILE_B + s0, Blo + gb0 + kc);
        cpa16(bb + 3 * TILE_B + s1, Blo + gb1 + kc);
        CP_COMMIT();
    };

    // ---- ldmatrix addressing (swizzled) -----------------------------------
    const uint32_t aRow = wm0 + (lane & 15);
    const uint32_t aChunkBase = (lane >> 4);
    const uint32_t aXor = (aRow >> 1) & 3;             // +16 rows: same xor
    const uint32_t g = lane >> 3;
    const uint32_t bRow = wn0 + (lane & 7) + ((g >> 1) << 3);
    const uint32_t bChunkBase = (g & 1);
    const uint32_t bXor = (bRow >> 1) & 3;

    float acc[2][8][4];
#pragma unroll
    for (int i = 0; i < 2; i++)
#pragma unroll
        for (int j = 0; j < 8; j++)
#pragma unroll
            for (int q = 0; q < 4; q++) acc[i][j][q] = 0.f;

    issue(0, 0);
    issue(1, 1);

    for (int kt = 0; kt < 32; kt++) {
        const int st = kt % NSTG;
        if (kt < 31) { CP_WAIT(1); } else { CP_WAIT(0); }
        __syncthreads();
        if (kt < 30) issue((kt + 2) % NSTG, kt + 2);

        const uint32_t base = smb + st * STAGE_B;
#pragma unroll
        for (int ksub = 0; ksub < 2; ksub++) {
            const uint32_t cA = (ksub * 2 + aChunkBase) ^ aXor;
            const uint32_t cB = (ksub * 2 + bChunkBase) ^ bXor;
            uint32_t ahi[2][4], alo[2][4];
#pragma unroll
            for (int mi = 0; mi < 2; mi++) {
                const uint32_t off = (aRow + mi * 16) * 64 + (cA << 4);
                ldsm4(ahi[mi][0], ahi[mi][1], ahi[mi][2], ahi[mi][3],
                      base + 0 * TILE_B + off);
                ldsm4(alo[mi][0], alo[mi][1], alo[mi][2], alo[mi][3],
                      base + 1 * TILE_B + off);
            }
#pragma unroll
            for (int pj = 0; pj < 4; pj++) {
                const uint32_t off = (bRow + pj * 16) * 64 + (cB << 4);
                uint32_t bh[4], bl[4];
                ldsm4(bh[0], bh[1], bh[2], bh[3], base + 2 * TILE_B + off);
                ldsm4(bl[0], bl[1], bl[2], bl[3], base + 3 * TILE_B + off);
#pragma unroll
                for (int mi = 0; mi < 2; mi++) {
                    MMA_BF16(acc[mi][2*pj],   ahi[mi], bh[0], bh[1]);
                    MMA_BF16(acc[mi][2*pj],   ahi[mi], bl[0], bl[1]);
                    MMA_BF16(acc[mi][2*pj],   alo[mi], bh[0], bh[1]);
                    MMA_BF16(acc[mi][2*pj+1], ahi[mi], bh[2], bh[3]);
                    MMA_BF16(acc[mi][2*pj+1], ahi[mi], bl[2], bl[3]);
                    MMA_BF16(acc[mi][2*pj+1], alo[mi], bh[2], bh[3]);
                }
            }
        }
    }

    // ---- epilogue ---------------------------------------------------------
#pragma unroll
    for (int mi = 0; mi < 2; mi++) {
#pragma unroll
        for (int nt = 0; nt < 8; nt++) {
            const int mrow0 = m0 + wm0 + mi * 16 + (lane >> 2);
            const int ncol  = n0 + wn0 + nt * 8 + (lane & 3) * 2;
            if (QKV) {
                const int h = ncol >> 6, d = ncol & 63;
#pragma unroll
                for (int half = 0; half < 2; half++) {
                    const int m = mrow0 + half * 8;
                    const int b = m >> 11, t = m & 2047;
                    const size_t off = (size_t)mat * KOFF
                                     + (((size_t)(b * HH + h) * TT + t) * DD + d);
                    uint32_t hh, ll;
                    split2(acc[mi][nt][half * 2] * preScale,
                           acc[mi][nt][half * 2 + 1] * preScale, hh, ll);
                    *(uint32_t*)(Chi + off) = hh;
                    *(uint32_t*)(Clo + off) = ll;
                }
            } else {
#pragma unroll
                for (int half = 0; half < 2; half++) {
                    float* o = C + (size_t)(mrow0 + half * 8) * NDIM + ncol;
                    *(float2*)o = make_float2(acc[mi][nt][half * 2],
                                              acc[mi][nt][half * 2 + 1]);
                }
            }
        }
    }
}

// ---------------------------------------------------------------------------
// HMMA flash attention. CTA = 128 q-rows, 8 warps, block 256, D=64.
// Q staged through stage 0 then recycled; 3-stage K/V cp.async ring.
// grid = (16 qtiles [reversed], 64 bh).
// ---------------------------------------------------------------------------
#define ASTRB    144
#define ATILE_B  (64 * ASTRB)              // 9216
#define ASTAGE_B (4 * ATILE_B)             // 36864
#define ASMEM_TOTAL (3 * ASTAGE_B)         // 110592

__global__ __launch_bounds__(256, 2)
void attn_mma(const __nv_bfloat16* __restrict__ QKVhi,
              const __nv_bfloat16* __restrict__ QKVlo,
              __nv_bfloat16* __restrict__ Yhi, __nv_bfloat16* __restrict__ Ylo)
{
    extern __shared__ __align__(128) char smA[];
    const int tid  = threadIdx.x;
    const int wid  = tid >> 5;
    const int lane = tid & 31;
    const int qt   = (int)(gridDim.x - 1) - (int)blockIdx.x;
    const int bh   = blockIdx.y;
    const int b    = bh >> 4;
    const int h    = bh & 15;
    const int q0   = qt * 128;

    const size_t bho = (size_t)bh * TT * DD;
    const __nv_bfloat16* qh = QKVhi + bho;
    const __nv_bfloat16* ql = QKVlo + bho;
    const __nv_bfloat16* kh = QKVhi + KOFF + bho;
    const __nv_bfloat16* kl = QKVlo + KOFF + bho;
    const __nv_bfloat16* vh = QKVhi + 2 * KOFF + bho;
    const __nv_bfloat16* vl = QKVlo + 2 * KOFF + bho;

    const uint32_t smb = smem_u32(smA);

    auto issue_stage = [&](int buf, int ktile) {
        const uint32_t sb = smb + buf * ASTAGE_B;
        const int k0 = ktile * 64;
#pragma unroll
        for (int i = 0; i < 2; i++) {
            const int c = tid + i * 256;           // 0..511
            const int r = c >> 3, col = c & 7;
            const uint32_t doff = r * ASTRB + col * 16;
            const size_t goff = (size_t)(k0 + r) * DD + col * 8;
            cpa16(sb + 0 * ATILE_B + doff, kh + goff);
            cpa16(sb + 1 * ATILE_B + doff, kl + goff);
            cpa16(sb + 2 * ATILE_B + doff, vh + goff);
            cpa16(sb + 3 * ATILE_B + doff, vl + goff);
        }
        CP_COMMIT();
    };

    // ---- stage Q through stage 0: hi -> tiles 0,1 ; lo -> tiles 2,3 -------
    {
#pragma unroll
        for (int i = 0; i < 4; i++) {
            const int c = tid + i * 256;           // 0..1023
            const int r = c >> 3, col = c & 7;     // r 0..127
            const uint32_t doff = (r >> 6) * ATILE_B + (r & 63) * ASTRB + col * 16;
            const size_t goff = (size_t)(q0 + r) * DD + col * 8;
            cpa16(smb + doff, qh + goff);
            cpa16(smb + 2 * ATILE_B + doff, ql + goff);
        }
        CP_COMMIT();
    }
    CP_WAIT(0);
    __syncthreads();

    // ---- persistent Q fragments -------------------------------------------
    const int l7  = lane & 7;
    const int l8  = (lane >> 3) & 1;
    const int l16 = lane >> 4;
    uint32_t qfh[4][4], qfl[4][4];
    {
        const uint32_t qrow = wid * 16 + l7 + l8 * 8;        // 0..127
        const uint32_t qbase = (qrow >> 6) * ATILE_B + (qrow & 63) * ASTRB;
#pragma unroll
        for (int kc = 0; kc < 4; kc++) {
            const uint32_t off = qbase + kc * 32 + l16 * 16;
            ldsm4(qfh[kc][0], qfh[kc][1], qfh[kc][2], qfh[kc][3], smb + off);
            ldsm4(qfl[kc][0], qfl[kc][1], qfl[kc][2], qfl[kc][3],
                  smb + 2 * ATILE_B + off);
        }
    }
    __syncthreads();          // Q reads done; stage 0 now reusable for K/V

    issue_stage(0, 0);
    issue_stage(1, 1);

    float accO[8][4];
    float mrow[2], lrow[2];
#pragma unroll
    for (int nt = 0; nt < 8; nt++)
#pragma unroll
        for (int q = 0; q < 4; q++) accO[nt][q] = 0.f;
    mrow[0] = mrow[1] = -1e30f;
    lrow[0] = lrow[1] = 0.f;

    const int rowg0 = q0 + wid * 16 + (lane >> 2);
    const int colg0 = (lane & 3) * 2;
    const int nk = 2 * (qt + 1);

    for (int kt = 0; kt < nk; kt++) {
        const int st = kt % 3;
        if (kt < nk - 1) { CP_WAIT(1); } else { CP_WAIT(0); }
        __syncthreads();
        if (kt + 2 < nk) issue_stage((kt + 2) % 3, kt + 2);

        const uint32_t base = smb + st * ASTAGE_B;

        // ---- S = Q K^T (3-term) -------------------------------------------
        float S[8][4];
#pragma unroll
        for (int nt = 0; nt < 8; nt++)
#pragma unroll
            for (int q = 0; q < 4; q++) S[nt][q] = 0.f;

        const uint32_t krow = l7 + l8 * 8;
#pragma unroll
        for (int kc = 0; kc < 4; kc++) {
#pragma unroll
            for (int p = 0; p < 4; p++) {
                const uint32_t off = (p * 16 + krow) * ASTRB + kc * 32 + l16 * 16;
                uint32_t b4h[4], b4l[4];
                ldsm4(b4h[0], b4h[1], b4h[2], b4h[3], base + 0 * ATILE_B + off);
                ldsm4(b4l[0], b4l[1], b4l[2], b4l[3], base + 1 * ATILE_B + off);
                MMA_BF16(S[2*p],   qfh[kc], b4h[0], b4h[2]);
                MMA_BF16(S[2*p],   qfh[kc], b4l[0], b4l[2]);
                MMA_BF16(S[2*p],   qfl[kc], b4h[0], b4h[2]);
                MMA_BF16(S[2*p+1], qfh[kc], b4h[1], b4h[3]);
                MMA_BF16(S[2*p+1], qfh[kc], b4l[1], b4l[3]);
                MMA_BF16(S[2*p+1], qfl[kc], b4h[1], b4h[3]);
            }
        }

        // ---- causal mask (only tiles crossing this warp's rows) -----------
        const int k0g = kt * 64;
        if (k0g + 63 > q0 + wid * 16) {
#pragma unroll
            for (int nt = 0; nt < 8; nt++) {
                const int cg = k0g + nt * 8 + colg0;
#pragma unroll
                for (int i = 0; i < 2; i++) {
                    const int rg = rowg0 + i * 8;
                    if (cg     > rg) S[nt][2*i]     = -1e30f;
                    if (cg + 1 > rg) S[nt][2*i + 1] = -1e30f;
                }
            }
        }

        // ---- online softmax (log2 units; scale folded into Q) -------------
#pragma unroll
        for (int i = 0; i < 2; i++) {
            float mx = -1e30f;
#pragma unroll
            for (int nt = 0; nt < 8; nt++)
                mx = fmaxf(mx, fmaxf(S[nt][2*i], S[nt][2*i+1]));
            mx = fmaxf(mx, __shfl_xor_sync(0xffffffffu, mx, 1));
            mx = fmaxf(mx, __shfl_xor_sync(0xffffffffu, mx, 2));
            const float mn = fmaxf(mrow[i], mx);
            const float fac = ex2f(mrow[i] - mn);
            float rs = 0.f;
#pragma unroll
            for (int nt = 0; nt < 8; nt++) {
                float p0 = ex2f(S[nt][2*i]   - mn);
                float p1 = ex2f(S[nt][2*i+1] - mn);
                S[nt][2*i] = p0; S[nt][2*i+1] = p1;
                rs += p0 + p1;
            }
            rs += __shfl_xor_sync(0xffffffffu, rs, 1);
            rs += __shfl_xor_sync(0xffffffffu, rs, 2);
            lrow[i] = lrow[i] * fac + rs;
            mrow[i] = mn;
#pragma unroll
            for (int nt = 0; nt < 8; nt++) {
                accO[nt][2*i]   *= fac;
                accO[nt][2*i+1] *= fac;
            }
        }

        // ---- O += P V (3-term), P packed in-register ----------------------
#pragma unroll
        for (int kc = 0; kc < 4; kc++) {
            uint32_t pah[4], pal[4];
            split2(S[2*kc][0],   S[2*kc][1],   pah[0], pal[0]);
            split2(S[2*kc][2],   S[2*kc][3],   pah[1], pal[1]);
            split2(S[2*kc+1][0], S[2*kc+1][1], pah[2], pal[2]);
            split2(S[2*kc+1][2], S[2*kc+1][3], pah[3], pal[3]);
#pragma unroll
            for (int p = 0; p < 4; p++) {
                const uint32_t off = (kc * 16 + krow) * ASTRB + p * 32 + l16 * 16;
                uint32_t v4h[4], v4l[4];
                ldsm4t(v4h[0], v4h[1], v4h[2], v4h[3], base + 2 * ATILE_B + off);
                ldsm4t(v4l[0], v4l[1], v4l[2], v4l[3], base + 3 * ATILE_B + off);
                MMA_BF16(accO[2*p],   pah, v4h[0], v4h[1]);
                MMA_BF16(accO[2*p],   pah, v4l[0], v4l[1]);
                MMA_BF16(accO[2*p],   pal, v4h[0], v4h[1]);
                MMA_BF16(accO[2*p+1], pah, v4h[2], v4h[3]);
                MMA_BF16(accO[2*p+1], pah, v4l[2], v4l[3]);
                MMA_BF16(accO[2*p+1], pal, v4h[2], v4h[3]);
            }
        }
    }

    // ---- epilogue: y[b,t,h*64+d] split bf16 -------------------------------
    const float inv0 = 1.0f / lrow[0];
    const float inv1 = 1.0f / lrow[1];
#pragma unroll
    for (int i = 0; i < 2; i++) {
        const float inv = i ? inv1 : inv0;
#pragma unroll
        for (int nt = 0; nt < 8; nt++) {
            const int d = nt * 8 + colg0;
            const size_t off = ((size_t)(b * TT + (rowg0 + i * 8))) * CC + h * DD + d;
            uint32_t hh, ll;
            split2(accO[nt][2*i] * inv, accO[nt][2*i+1] * inv, hh, ll);
            *(uint32_t*)(Yhi + off) = hh;
            *(uint32_t*)(Ylo + off) = ll;
        }
    }
}

// ---------------------------------------------------------------------------
// launch
// ---------------------------------------------------------------------------
extern "C" void kernel_launch(void* const* d_in, const int* in_sizes, int n_in,
                              void* d_out, int out_size)
{
    const float* x_q = (const float*)d_in[0];
    const float* w_q = (const float*)d_in[1];
    const float* w_k = (const float*)d_in[2];
    const float* w_v = (const float*)d_in[3];
    const float* w_o = (const float*)d_in[4];
    float* out = (float*)d_out;

    __nv_bfloat16 *qkvhi, *qkvlo, *xhi, *xlo, *yhi, *ylo;
    __nv_bfloat16 *wallhi, *walllo, *wohi, *wolo;
    cudaGetSymbolAddress((void**)&qkvhi, g_qkvhi);
    cudaGetSymbolAddress((void**)&qkvlo, g_qkvlo);
    cudaGetSymbolAddress((void**)&xhi, g_xhi);   cudaGetSymbolAddress((void**)&xlo, g_xlo);
    cudaGetSymbolAddress((void**)&yhi, g_yhi);   cudaGetSymbolAddress((void**)&ylo, g_ylo);
    cudaGetSymbolAddress((void**)&wallhi, g_wallhi);
    cudaGetSymbolAddress((void**)&walllo, g_walllo);
    cudaGetSymbolAddress((void**)&wohi, g_wohi); cudaGetSymbolAddress((void**)&wolo, g_wolo);

    const int smemG = NSTG * STAGE_B;   // 98304
    cudaFuncSetAttribute(hmma_gemm<true>,  cudaFuncAttributeMaxDynamicSharedMemorySize, smemG);
    cudaFuncSetAttribute(hmma_gemm<false>, cudaFuncAttributeMaxDynamicSharedMemorySize, smemG);
    cudaFuncSetAttribute(attn_mma, cudaFuncAttributeMaxDynamicSharedMemorySize, ASMEM_TOTAL);

    // splits
    split_kernel<<<(MROWS * KDIM / 4 + 255) / 256, 256>>>(x_q, xhi, xlo, MROWS * KDIM);
    split_w3<<<dim3(NDIM * KDIM / 4 / 256, 3), 256>>>(w_q, w_k, w_v, wallhi, walllo);
    split_transpose<<<dim3(32, 32), dim3(32, 32)>>>(w_o, wohi, wolo);

    // fused QKV projection
    dim3 gridQKV(MROWS / 128, 24);
    hmma_gemm<true><<<gridQKV, 256, smemG>>>(xhi, xlo, wallhi, walllo,
                                             nullptr, qkvhi, qkvlo);

    // attention
    dim3 gridA(TT / 128, BB * HH);
    attn_mma<<<gridA, 256, ASMEM_TOTAL>>>(qkvhi, qkvlo, yhi, ylo);

    // output projection
    dim3 gridO(MROWS / 128, NDIM / 128);
    hmma_gemm<false><<<gridO, 256, smemG>>>(yhi, ylo, wohi, wolo,
                                            out, nullptr, nullptr);
}